// round 13
// baseline (speedup 1.0000x reference)
#include <cuda_runtime.h>
#include <cuda_fp16.h>
#include <math.h>
#include <cstdint>

#define BB 8
#define TT 1024
#define LLn 4
#define IIn 4
#define HH 768
#define NHEAD 4
#define DH 192
#define NLAY 3
#define NN (TT+LLn+IIn)      /* 1032 */
#define MROWS (BB*NN)        /* 8256 */

__device__ float g_h [MROWS*HH];
__device__ float g_hw[MROWS*HH];
__device__ float g_es[MROWS*NHEAD];
__device__ float g_ed[MROWS*NHEAD];
__device__ int   g_minL[BB*TT];
__device__ int   g_minI[BB*TT];
__device__ float g_nrm[BB*8];
__device__ float g_m[BB*8*NHEAD];
__device__ float g_s[BB*8*NHEAD];
__device__ float g_agg[BB*8*HH];

// fp16 operands
__device__ __half g_hh[MROWS*HH];
__device__ __half g_wh[NLAY*HH*HH];   // transposed: [n][k]

__device__ __forceinline__ float lrelu(float x){ return x>0.f ? x : 0.2f*x; }

// ---------------- pack inputs into node state (+fp16) ----------------
__global__ void k_pack(const float* __restrict__ text,const float* __restrict__ lab,
                       const float* __restrict__ img){
  int idx = blockIdx.x*256 + threadIdx.x;
  if (idx >= MROWS*HH) return;
  int c = idx % HH;
  int n = (idx / HH) % NN;
  int b = idx / (NN*HH);
  float v;
  if (n < TT)            v = text[((size_t)b*TT + n)*HH + c];
  else if (n < TT+LLn)   v = lab [((size_t)b*LLn + (n-TT))*HH + c];
  else                   v = img [((size_t)b*IIn + (n-TT-LLn))*HH + c];
  g_h[idx] = v;
  g_hh[idx] = __float2half(v);
}

// ---------------- convert weights: transpose + fp16 (all layers) ----------------
__global__ void k_cvtW(const float* __restrict__ W){
  __shared__ float tile[32][33];
  int l = blockIdx.z;
  int n0 = blockIdx.x*32, k0 = blockIdx.y*32;
  const float* Wl = W + (size_t)l*HH*HH;
  tile[threadIdx.y][threadIdx.x] = Wl[(size_t)(k0+threadIdx.y)*HH + n0+threadIdx.x];
  __syncthreads();
  float x = tile[threadIdx.x][threadIdx.y];
  size_t o = (size_t)l*HH*HH + (size_t)(n0+threadIdx.y)*HH + (k0+threadIdx.x);
  g_wh[o] = __float2half(x);
}

// ---------------- zero es/ed before GEMM's fused atomic reduction ----------------
__global__ void k_zero(){
  int i = blockIdx.x*256 + threadIdx.x;
  if (i < MROWS*NHEAD){ g_es[i]=0.f; g_ed[i]=0.f; }
}

// ---------------- per-sample label/image norms ----------------
__global__ void k_norm(const float* __restrict__ lab,const float* __restrict__ img){
  int b = blockIdx.x / 8, j = blockIdx.x % 8;
  const float* row = (j<LLn) ? (lab + ((size_t)b*LLn + j)*HH)
                             : (img + ((size_t)b*IIn + (j-LLn))*HH);
  float s = 0.f;
  for (int c=threadIdx.x; c<HH; c+=128){ float v=row[c]; s += v*v; }
  __shared__ float red[128];
  red[threadIdx.x]=s; __syncthreads();
  for (int st=64; st>0; st>>=1){
    if (threadIdx.x<st) red[threadIdx.x]+=red[threadIdx.x+st];
    __syncthreads();
  }
  if (threadIdx.x==0) g_nrm[blockIdx.x] = sqrtf(red[0]);
}

// ---------------- top-k (store excluded argmin), float4 loads ----------------
__global__ void k_topk(const float* __restrict__ text,const float* __restrict__ lab,
                       const float* __restrict__ img){
  int bt = blockIdx.x;
  int b = bt / TT, t = bt % TT;
  const float4* trow = (const float4*)(text + ((size_t)b*TT + t)*HH);
  const float4* lb = (const float4*)(lab + (size_t)b*LLn*HH);
  const float4* im = (const float4*)(img + (size_t)b*IIn*HH);
  float acc[9];
  #pragma unroll
  for (int i=0;i<9;i++) acc[i]=0.f;
  for (int c=threadIdx.x; c<HH/4; c+=128){
    float4 tv = trow[c];
    acc[0] += tv.x*tv.x + tv.y*tv.y + tv.z*tv.z + tv.w*tv.w;
    #pragma unroll
    for (int j=0;j<4;j++){
      float4 lv = lb[j*(HH/4)+c];
      acc[1+j] += tv.x*lv.x + tv.y*lv.y + tv.z*lv.z + tv.w*lv.w;
    }
    #pragma unroll
    for (int j=0;j<4;j++){
      float4 iv = im[j*(HH/4)+c];
      acc[5+j] += tv.x*iv.x + tv.y*iv.y + tv.z*iv.z + tv.w*iv.w;
    }
  }
  __shared__ float red[9][4];
  int lane=threadIdx.x&31, w=threadIdx.x>>5;
  #pragma unroll
  for (int i=0;i<9;i++){
    float v=acc[i];
    for (int o=16;o>0;o>>=1) v += __shfl_down_sync(0xffffffffu,v,o);
    if (lane==0) red[i][w]=v;
  }
  __syncthreads();
  if (threadIdx.x==0){
    float tot[9];
    #pragma unroll
    for (int i=0;i<9;i++) tot[i]=red[i][0]+red[i][1]+red[i][2]+red[i][3];
    float tn = sqrtf(tot[0]);
    int amL=0; float mvL=3.4e38f;
    for (int j=0;j<4;j++){
      float den = fmaxf(tn*g_nrm[b*8+j], 1e-8f);
      float s = tot[1+j]/den;
      if (s<mvL){ mvL=s; amL=j; }
    }
    g_minL[bt]=amL;
    int amI=0; float mvI=3.4e38f;
    for (int j=0;j<4;j++){
      float den = fmaxf(tn*g_nrm[b*8+4+j], 1e-8f);
      float s = tot[5+j]/den;
      if (s<mvI){ mvI=s; amI=j; }
    }
    g_minI[bt]=amI;
  }
}

// ======================= HMMA GEMM (M128xN128, pure fp16, 3-buffer pipeline) =======================
#define APAD 40
#define TILE_E (128*APAD)
#define BUF_E  (2*TILE_E)
#define NBUF 3
#define GEMM_SMEM (NBUF*BUF_E*2)   /* 61440 bytes */

__device__ __forceinline__ uint32_t smem_u32(const void* p){
  return (uint32_t)__cvta_generic_to_shared(p);
}
__device__ __forceinline__ void cp16(uint32_t dst, const void* src){
  asm volatile("cp.async.cg.shared.global [%0], [%1], 16;" :: "r"(dst), "l"(src));
}
__device__ __forceinline__ void cp_commit(){ asm volatile("cp.async.commit_group;"); }
__device__ __forceinline__ void cp_wait1(){ asm volatile("cp.async.wait_group 1;"); }
__device__ __forceinline__ void cp_wait0(){ asm volatile("cp.async.wait_group 0;"); }
__device__ __forceinline__ void ldmx4(uint32_t a, uint32_t& r0, uint32_t& r1, uint32_t& r2, uint32_t& r3){
  asm volatile("ldmatrix.sync.aligned.m8n8.x4.shared.b16 {%0,%1,%2,%3}, [%4];"
    : "=r"(r0), "=r"(r1), "=r"(r2), "=r"(r3) : "r"(a));
}
__device__ __forceinline__ void mma16816(float* d, const uint32_t* a, uint32_t b0, uint32_t b1){
  asm volatile(
    "mma.sync.aligned.m16n8k16.row.col.f32.f16.f16.f32 "
    "{%0,%1,%2,%3}, {%4,%5,%6,%7}, {%8,%9}, {%0,%1,%2,%3};"
    : "+f"(d[0]), "+f"(d[1]), "+f"(d[2]), "+f"(d[3])
    : "r"(a[0]), "r"(a[1]), "r"(a[2]), "r"(a[3]), "r"(b0), "r"(b1));
}

__global__ void __launch_bounds__(256,2) k_gemm_mma(int layer,
    const float* __restrict__ asrc, const float* __restrict__ adst){
  extern __shared__ __half sm[];

  int tid = threadIdx.x;
  int wid = tid >> 5, lane = tid & 31;
  int wm = wid & 3, wn = wid >> 2;        // warp tile 32 rows x 64 cols
  int bx = blockIdx.x;                     // n tile 0..5
  int by = blockIdx.y;                     // m tile 0..64

  const __half* wH = g_wh + (size_t)layer*HH*HH;

  int r0 = tid >> 2, r1 = 64 + (tid >> 2);
  int c8 = (tid & 3) * 8;
  int mA0 = by*128 + r0; if (mA0 >= MROWS) mA0 = MROWS-1;
  int mA1 = by*128 + r1; if (mA1 >= MROWS) mA1 = MROWS-1;
  int nB0 = bx*128 + r0;
  int nB1 = bx*128 + 64 + r0;
  uint32_t sBase = smem_u32(sm);
  uint32_t d0 = (uint32_t)(r0*APAD + c8)*2;
  uint32_t d1 = (uint32_t)(r1*APAD + c8)*2;

  uint32_t aRow = (uint32_t)(wm*32 + ((lane>>3)&1)*8 + (lane&7));
  uint32_t aCol = (uint32_t)(((lane>>4)&1)*8);
  uint32_t bRow = (uint32_t)(wn*64 + ((lane>>4)&1)*8 + (lane&7));
  uint32_t bCol = (uint32_t)(((lane>>3)&1)*8);

  float acc[2][8][4];
  #pragma unroll
  for (int i=0;i<2;i++)
    #pragma unroll
    for (int j=0;j<8;j++)
      #pragma unroll
      for (int k=0;k<4;k++) acc[i][j][k]=0.f;

  const int NSTAGE = 24;
  auto issue = [&](int s){
    int k0 = s * 32;
    uint32_t off = sBase + (uint32_t)((s % NBUF) * BUF_E) * 2;
    cp16(off + 0*TILE_E*2 + d0, g_hh + (size_t)mA0*HH + k0 + c8);
    cp16(off + 0*TILE_E*2 + d1, g_hh + (size_t)mA1*HH + k0 + c8);
    cp16(off + 1*TILE_E*2 + d0, wH + (size_t)nB0*HH + k0 + c8);
    cp16(off + 1*TILE_E*2 + d1, wH + (size_t)nB1*HH + k0 + c8);
    cp_commit();
  };

  issue(0);
  issue(1);
  for (int s = 0; s < NSTAGE; s++){
    if (s+2 < NSTAGE) cp_wait1(); else cp_wait0();
    __syncthreads();           // compute of s-1 done by all warps; buffer (s+2)%3 free
    if (s+2 < NSTAGE) issue(s+2);
    uint32_t buf = sBase + (uint32_t)((s % NBUF) * BUF_E) * 2;
    uint32_t tA = buf, tB = buf + TILE_E*2;
    #pragma unroll
    for (int kk = 0; kk < 32; kk += 16){
      uint32_t a[2][4], b[4][4];
      #pragma unroll
      for (int mt=0; mt<2; mt++){
        uint32_t ro = ((aRow + mt*16)*APAD + aCol + kk)*2;
        ldmx4(tA + ro, a[mt][0], a[mt][1], a[mt][2], a[mt][3]);
      }
      #pragma unroll
      for (int nt=0; nt<4; nt++){
        uint32_t ro = ((bRow + nt*16)*APAD + bCol + kk)*2;
        ldmx4(tB + ro, b[nt][0], b[nt][1], b[nt][2], b[nt][3]);
      }
      #pragma unroll
      for (int mt=0; mt<2; mt++)
        #pragma unroll
        for (int n=0; n<8; n++){
          int nt = n >> 1, pr = n & 1;
          mma16816(acc[mt][n], a[mt], b[nt][pr*2], b[nt][pr*2+1]);
        }
    }
  }

  // epilogue 1: write accumulators to g_hw
  #pragma unroll
  for (int mt=0; mt<2; mt++){
    int rr = by*128 + wm*32 + mt*16 + (lane>>2);
    #pragma unroll
    for (int n=0; n<8; n++){
      int c0 = bx*128 + wn*64 + n*8 + (lane&3)*2;
      if (rr < MROWS)
        *(float2*)(g_hw + (size_t)rr*HH + c0) = make_float2(acc[mt][n][0], acc[mt][n][1]);
      if (rr+8 < MROWS)
        *(float2*)(g_hw + (size_t)(rr+8)*HH + c0) = make_float2(acc[mt][n][2], acc[mt][n][3]);
    }
  }

  // epilogue 2: fused es/ed reduction. This warp's 64 cols lie in one head.
  int head = (bx*128 + wn*64) / DH;
  #pragma unroll
  for (int mt=0; mt<2; mt++){
    float ses0=0.f, sed0=0.f, ses1=0.f, sed1=0.f;
    #pragma unroll
    for (int n=0; n<8; n++){
      int c = bx*128 + wn*64 + n*8 + (lane&3)*2;
      float a0=asrc[c], a1=asrc[c+1], dd0=adst[c], dd1=adst[c+1];
      ses0 += acc[mt][n][0]*a0 + acc[mt][n][1]*a1;
      sed0 += acc[mt][n][0]*dd0 + acc[mt][n][1]*dd1;
      ses1 += acc[mt][n][2]*a0 + acc[mt][n][3]*a1;
      sed1 += acc[mt][n][2]*dd0 + acc[mt][n][3]*dd1;
    }
    #pragma unroll
    for (int o=1; o<=2; o<<=1){
      ses0 += __shfl_xor_sync(0xffffffffu, ses0, o);
      sed0 += __shfl_xor_sync(0xffffffffu, sed0, o);
      ses1 += __shfl_xor_sync(0xffffffffu, ses1, o);
      sed1 += __shfl_xor_sync(0xffffffffu, sed1, o);
    }
    if ((lane&3)==0){
      int rr = by*128 + wm*32 + mt*16 + (lane>>2);
      if (rr < MROWS){
        atomicAdd(&g_es[rr*NHEAD+head], ses0);
        atomicAdd(&g_ed[rr*NHEAD+head], sed0);
      }
      if (rr+8 < MROWS){
        atomicAdd(&g_es[(rr+8)*NHEAD+head], ses1);
        atomicAdd(&g_ed[(rr+8)*NHEAD+head], sed1);
      }
    }
  }
}

// 8 static in-edges for big node j (0..3 = label j, 4..7 = image j-4)
__device__ __forceinline__ int static_src(int j,int s){
  if (j<LLn){
    if (s<4) return TT+LLn+s;
    if (s<7){ int p=s-4; if(p>=j)p++; return TT+p; }
    return TT+j;
  } else {
    int jj=j-LLn;
    if (s<4) return TT+s;
    if (s<7){ int p=s-4; if(p>=jj)p++; return TT+LLn+p; }
    return TT+LLn+jj;
  }
}

// ---------------- big-node softmax max & sumexp (and zero agg) ----------------
__global__ void k_ms(){
  int b = blockIdx.x>>3, j = blockIdx.x&7;
  int tid = threadIdx.x;
  int jj = (j<LLn)? j : j-LLn;
  int dst = (j<LLn)? (TT+j) : (TT+LLn+jj);
  for (int c=tid;c<HH;c+=256) g_agg[blockIdx.x*HH+c]=0.f;
  float edv[4];
  #pragma unroll
  for (int h=0;h<4;h++) edv[h]=g_ed[(size_t)(b*NN+dst)*NHEAD+h];
  const int* minA = (j<LLn)? (g_minL+b*TT) : (g_minI+b*TT);
  float mx[4]={-3.4e38f,-3.4e38f,-3.4e38f,-3.4e38f};
  for (int t=tid;t<TT;t+=256){
    if (minA[t]!=jj){
      const float* e = g_es + (size_t)(b*NN+t)*NHEAD;
      #pragma unroll
      for (int h=0;h<4;h++) mx[h]=fmaxf(mx[h], lrelu(e[h]+edv[h]));
    }
  }
  if (tid==0){
    #pragma unroll
    for (int s=0;s<8;s++){
      int sr = static_src(j,s);
      const float* e = g_es + (size_t)(b*NN+sr)*NHEAD;
      #pragma unroll
      for (int h=0;h<4;h++) mx[h]=fmaxf(mx[h], lrelu(e[h]+edv[h]));
    }
  }
  __shared__ float red[256][4];
  #pragma unroll
  for (int h=0;h<4;h++) red[tid][h]=mx[h];
  __syncthreads();
  for (int st=128;st>0;st>>=1){
    if (tid<st){
      #pragma unroll
      for (int h=0;h<4;h++) red[tid][h]=fmaxf(red[tid][h],red[tid+st][h]);
    }
    __syncthreads();
  }
  float mv[4];
  #pragma unroll
  for (int h=0;h<4;h++) mv[h]=red[0][h];
  __syncthreads();
  float sm[4]={0.f,0.f,0.f,0.f};
  for (int t=tid;t<TT;t+=256){
    if (minA[t]!=jj){
      const float* e = g_es + (size_t)(b*NN+t)*NHEAD;
      #pragma unroll
      for (int h=0;h<4;h++) sm[h] += __expf(lrelu(e[h]+edv[h])-mv[h]);
    }
  }
  if (tid==0){
    #pragma unroll
    for (int s=0;s<8;s++){
      int sr = static_src(j,s);
      const float* e = g_es + (size_t)(b*NN+sr)*NHEAD;
      #pragma unroll
      for (int h=0;h<4;h++) sm[h] += __expf(lrelu(e[h]+edv[h])-mv[h]);
    }
  }
  #pragma unroll
  for (int h=0;h<4;h++) red[tid][h]=sm[h];
  __syncthreads();
  for (int st=128;st>0;st>>=1){
    if (tid<st){
      #pragma unroll
      for (int h=0;h<4;h++) red[tid][h]+=red[tid+st][h];
    }
    __syncthreads();
  }
  if (tid<4){
    g_m[(b*8+j)*NHEAD+tid]=mv[tid];
    g_s[(b*8+j)*NHEAD+tid]=red[0][tid];
  }
}

// ---------------- big-node weighted aggregation (all 8 j per block, alpha inline) ----------------
__global__ void k_agg(){
  int b  = blockIdx.x >> 5;
  int sp = blockIdx.x & 31;
  int tid = threadIdx.x;
  int t0 = sp*32;
  __shared__ float sal[32][8][4];
  #pragma unroll
  for (int q=0;q<4;q++){
    int idx = tid + q*256;
    int tl = idx >> 5;
    int j  = (idx >> 2) & 7;
    int h  = idx & 3;
    int jj = (j<LLn)? j : j-LLn;
    int dst = (j<LLn)? (TT+j) : (TT+LLn+jj);
    int t = t0 + tl;
    int excl = (j<LLn)? (g_minL[b*TT+t]==jj) : (g_minI[b*TT+t]==jj);
    float al = 0.f;
    if (!excl){
      float e = lrelu(g_es[(size_t)(b*NN+t)*NHEAD+h] + g_ed[(size_t)(b*NN+dst)*NHEAD+h]);
      al = __expf(e - g_m[(b*8+j)*NHEAD+h]) / g_s[(b*8+j)*NHEAD+h];
    }
    sal[tl][j][h] = al;
  }
  __syncthreads();
  int c0=tid, c1=tid+256, c2=tid+512;
  int h0=c0/DH, h1=c1/DH, h2=c2/DH;
  float a0[8], a1[8], a2[8];
  #pragma unroll
  for (int j=0;j<8;j++){ a0[j]=0.f; a1[j]=0.f; a2[j]=0.f; }
  for (int tl=0; tl<32; tl++){
    const float* hr = g_hw + (size_t)(b*NN + t0+tl)*HH;
    float v0=hr[c0], v1=hr[c1], v2=hr[c2];
    #pragma unroll
    for (int j=0;j<8;j++){
      a0[j] += sal[tl][j][h0]*v0;
      a1[j] += sal[tl][j][h1]*v1;
      a2[j] += sal[tl][j][h2]*v2;
    }
  }
  #pragma unroll
  for (int j=0;j<8;j++){
    atomicAdd(&g_agg[(b*8+j)*HH+c0], a0[j]);
    atomicAdd(&g_agg[(b*8+j)*HH+c1], a1[j]);
    atomicAdd(&g_agg[(b*8+j)*HH+c2], a2[j]);
  }
}

// ---------------- big-node epilogue: static edges + bias+relu+residual+LN (+conv) ----------------
__global__ void k_big(const float* __restrict__ bias,const float* __restrict__ lng,
                      const float* __restrict__ lnb){
  int b = blockIdx.x>>3, j = blockIdx.x&7;
  int jj = (j<LLn)? j : j-LLn;
  int node = (j<LLn)? (TT+j) : (TT+LLn+jj);
  int tid = threadIdx.x;
  __shared__ float sal[8][4];
  __shared__ int ssrc[8];
  if (tid<32){
    int s=tid>>2, h=tid&3;
    int sr = static_src(j,s);
    if (h==0) ssrc[s]=sr;
    float e = lrelu(g_es[(size_t)(b*NN+sr)*NHEAD+h] + g_ed[(size_t)(b*NN+node)*NHEAD+h]);
    sal[s][h] = __expf(e - g_m[(b*8+j)*NHEAD+h]) / g_s[(b*8+j)*NHEAD+h];
  }
  __syncthreads();
  size_t row = (size_t)(b*NN+node)*HH;
  float v[3]; float s=0.f, sq=0.f;
  #pragma unroll
  for (int r=0;r<3;r++){
    int c = tid + 256*r;
    int hd = c/DH;
    float o = g_agg[(b*8+j)*HH+c];
    #pragma unroll
    for (int e=0;e<8;e++)
      o += sal[e][hd] * g_hw[(size_t)(b*NN+ssrc[e])*HH + c];
    o = fmaxf(o + bias[c], 0.f);
    float y = o + g_h[row+c];
    v[r]=y; s+=y; sq+=y*y;
  }
  __shared__ float rs[256], rq[256];
  rs[tid]=s; rq[tid]=sq; __syncthreads();
  for (int st=128;st>0;st>>=1){
    if (tid<st){ rs[tid]+=rs[tid+st]; rq[tid]+=rq[tid+st]; }
    __syncthreads();
  }
  float mu = rs[0]*(1.f/HH);
  float var = rq[0]*(1.f/HH) - mu*mu;
  float rstd = rsqrtf(var + 1e-5f);
  #pragma unroll
  for (int r=0;r<3;r++){
    int c = tid + 256*r;
    float y = (v[r]-mu)*rstd*lng[c] + lnb[c];
    g_h[row+c] = y;
    g_hh[row+c] = __float2half(y);
  }
}

// ---------------- text-node: full fused attention + epilogue (R6 proven) ----------------
__global__ void k_text(const float* __restrict__ bias,const float* __restrict__ lng,
                       const float* __restrict__ lnb, float* __restrict__ outp, int last){
  int bt = blockIdx.x;
  int b = bt/TT, t = bt%TT;
  int tid = threadIdx.x;
  __shared__ int ssrc[9];
  __shared__ int snum;
  __shared__ float sal[9][4];
  if (tid==0){
    int n=0;
    ssrc[n++]=t;
    if (t>0)    ssrc[n++]=t-1;
    if (t<TT-1) ssrc[n++]=t+1;
    int ml=g_minL[bt], mi=g_minI[bt];
    #pragma unroll
    for (int j2=0;j2<4;j2++) if (j2!=ml) ssrc[n++]=TT+j2;
    #pragma unroll
    for (int j2=0;j2<4;j2++) if (j2!=mi) ssrc[n++]=TT+LLn+j2;
    snum=n;
  }
  __syncthreads();
  int ns = snum;
  if (tid<4){
    float ed = g_ed[(size_t)(b*NN+t)*NHEAD + tid];
    float ev[9]; float mxv=-3.4e38f;
    for (int e=0;e<ns;e++){
      float x = lrelu(g_es[(size_t)(b*NN+ssrc[e])*NHEAD + tid] + ed);
      ev[e]=x; mxv=fmaxf(mxv,x);
    }
    float sm=0.f;
    for (int e=0;e<ns;e++){ float w=__expf(ev[e]-mxv); ev[e]=w; sm+=w; }
    float inv = 1.f/sm;
    for (int e=0;e<ns;e++) sal[e][tid]=ev[e]*inv;
  }
  __syncthreads();
  size_t row = (size_t)(b*NN+t)*HH;
  float v[3]; float s=0.f, sq=0.f;
  #pragma unroll
  for (int r=0;r<3;r++){
    int c = tid + 256*r;
    int hd = c/DH;
    float a = 0.f;
    for (int e=0;e<ns;e++)
      a += sal[e][hd] * g_hw[(size_t)(b*NN+ssrc[e])*HH + c];
    float o = fmaxf(a + bias[c], 0.f);
    float y = o + g_h[row+c];
    v[r]=y; s+=y; sq+=y*y;
  }
  __shared__ float rs[256], rq[256];
  rs[tid]=s; rq[tid]=sq; __syncthreads();
  for (int st=128;st>0;st>>=1){
    if (tid<st){ rs[tid]+=rs[tid+st]; rq[tid]+=rq[tid+st]; }
    __syncthreads();
  }
  float mu = rs[0]*(1.f/HH);
  float var = rq[0]*(1.f/HH) - mu*mu;
  float rstd = rsqrtf(var + 1e-5f);
  if (last){
    float* od = outp + ((size_t)b*TT + t)*HH;
    #pragma unroll
    for (int r=0;r<3;r++){
      int c = tid + 256*r;
      od[c] = (v[r]-mu)*rstd*lng[c] + lnb[c];
    }
  } else {
    #pragma unroll
    for (int r=0;r<3;r++){
      int c = tid + 256*r;
      float y = (v[r]-mu)*rstd*lng[c] + lnb[c];
      g_h[row+c] = y;
      g_hh[row+c] = __float2half(y);
    }
  }
}

extern "C" void kernel_launch(void* const* d_in, const int* in_sizes, int n_in,
                              void* d_out, int out_size) {
  const float* text = (const float*)d_in[0];
  const float* lab  = (const float*)d_in[1];
  const float* img  = (const float*)d_in[2];
  const float* W    = (const float*)d_in[3];
  const float* asrc = (const float*)d_in[4];
  const float* adst = (const float*)d_in[5];
  const float* bias = (const float*)d_in[6];
  const float* lng  = (const float*)d_in[7];
  const float* lnb  = (const float*)d_in[8];
  float* out = (float*)d_out;

  cudaFuncSetAttribute(k_gemm_mma, cudaFuncAttributeMaxDynamicSharedMemorySize, GEMM_SMEM);

  // launch order keeps the GEMM at profiled slot 4
  k_zero<<<(MROWS*NHEAD+255)/256, 256>>>();
  k_pack<<<(MROWS*HH+255)/256, 256>>>(text, lab, img);
  k_cvtW<<<dim3(24,24,3), dim3(32,32)>>>(W);
  k_gemm_mma<<<dim3(6,65), 256, GEMM_SMEM>>>(0, asrc, adst);
  k_norm<<<BB*8, 128>>>(lab, img);
  k_topk<<<BB*TT, 128>>>(text, lab, img);

  for (int l=0; l<NLAY; l++){
    int last = (l == NLAY-1);
    if (l > 0){
      k_zero<<<(MROWS*NHEAD+255)/256, 256>>>();
      k_gemm_mma<<<dim3(6,65), 256, GEMM_SMEM>>>(l, asrc + l*NHEAD*DH, adst + l*NHEAD*DH);
    }
    if (!last){
      k_ms<<<BB*8, 256>>>();
      k_agg<<<BB*32, 256>>>();
      k_big<<<BB*8, 256>>>(bias + l*HH, lng + l*HH, lnb + l*HH);
    }
    k_text<<<BB*TT, 256>>>(bias + l*HH, lng + l*HH, lnb + l*HH, out, last);
  }
}

// round 14
// speedup vs baseline: 1.0521x; 1.0521x over previous
#include <cuda_runtime.h>
#include <cuda_fp16.h>
#include <math.h>
#include <cstdint>

#define BB 8
#define TT 1024
#define LLn 4
#define IIn 4
#define HH 768
#define NHEAD 4
#define DH 192
#define NLAY 3
#define NN (TT+LLn+IIn)      /* 1032 */
#define MROWS (BB*NN)        /* 8256 */

__device__ float g_h [MROWS*HH];
__device__ float g_hw[MROWS*HH];
__device__ float g_es[MROWS*NHEAD];
__device__ float g_ed[MROWS*NHEAD];
__device__ int   g_minL[BB*TT];
__device__ int   g_minI[BB*TT];
__device__ float g_nrm[BB*8];
__device__ float g_m[BB*8*NHEAD];
__device__ float g_s[BB*8*NHEAD];
__device__ float g_agg[BB*8*HH];

// fp16 operands
__device__ __half g_hh[MROWS*HH];
__device__ __half g_wh[NLAY*HH*HH];   // transposed: [n][k]

__device__ __forceinline__ float lrelu(float x){ return x>0.f ? x : 0.2f*x; }

// ---------------- pack inputs into node state (+fp16) ----------------
__global__ void k_pack(const float* __restrict__ text,const float* __restrict__ lab,
                       const float* __restrict__ img){
  int idx = blockIdx.x*256 + threadIdx.x;
  if (idx >= MROWS*HH) return;
  int c = idx % HH;
  int n = (idx / HH) % NN;
  int b = idx / (NN*HH);
  float v;
  if (n < TT)            v = text[((size_t)b*TT + n)*HH + c];
  else if (n < TT+LLn)   v = lab [((size_t)b*LLn + (n-TT))*HH + c];
  else                   v = img [((size_t)b*IIn + (n-TT-LLn))*HH + c];
  g_h[idx] = v;
  g_hh[idx] = __float2half(v);
}

// ---------------- convert weights: transpose + fp16 (all layers) ----------------
__global__ void k_cvtW(const float* __restrict__ W){
  __shared__ float tile[32][33];
  int l = blockIdx.z;
  int n0 = blockIdx.x*32, k0 = blockIdx.y*32;
  const float* Wl = W + (size_t)l*HH*HH;
  tile[threadIdx.y][threadIdx.x] = Wl[(size_t)(k0+threadIdx.y)*HH + n0+threadIdx.x];
  __syncthreads();
  float x = tile[threadIdx.x][threadIdx.y];
  size_t o = (size_t)l*HH*HH + (size_t)(n0+threadIdx.y)*HH + (k0+threadIdx.x);
  g_wh[o] = __float2half(x);
}

// ---------------- zero es/ed before GEMM's fused atomic reduction ----------------
__global__ void k_zero(){
  int i = blockIdx.x*256 + threadIdx.x;
  if (i < MROWS*NHEAD){ g_es[i]=0.f; g_ed[i]=0.f; }
}

// ---------------- per-sample label/image norms ----------------
__global__ void k_norm(const float* __restrict__ lab,const float* __restrict__ img){
  int b = blockIdx.x / 8, j = blockIdx.x % 8;
  const float* row = (j<LLn) ? (lab + ((size_t)b*LLn + j)*HH)
                             : (img + ((size_t)b*IIn + (j-LLn))*HH);
  float s = 0.f;
  for (int c=threadIdx.x; c<HH; c+=128){ float v=row[c]; s += v*v; }
  __shared__ float red[128];
  red[threadIdx.x]=s; __syncthreads();
  for (int st=64; st>0; st>>=1){
    if (threadIdx.x<st) red[threadIdx.x]+=red[threadIdx.x+st];
    __syncthreads();
  }
  if (threadIdx.x==0) g_nrm[blockIdx.x] = sqrtf(red[0]);
}

// ---------------- top-k (store excluded argmin), float4 loads ----------------
__global__ void k_topk(const float* __restrict__ text,const float* __restrict__ lab,
                       const float* __restrict__ img){
  int bt = blockIdx.x;
  int b = bt / TT, t = bt % TT;
  const float4* trow = (const float4*)(text + ((size_t)b*TT + t)*HH);
  const float4* lb = (const float4*)(lab + (size_t)b*LLn*HH);
  const float4* im = (const float4*)(img + (size_t)b*IIn*HH);
  float acc[9];
  #pragma unroll
  for (int i=0;i<9;i++) acc[i]=0.f;
  for (int c=threadIdx.x; c<HH/4; c+=128){
    float4 tv = trow[c];
    acc[0] += tv.x*tv.x + tv.y*tv.y + tv.z*tv.z + tv.w*tv.w;
    #pragma unroll
    for (int j=0;j<4;j++){
      float4 lv = lb[j*(HH/4)+c];
      acc[1+j] += tv.x*lv.x + tv.y*lv.y + tv.z*lv.z + tv.w*lv.w;
    }
    #pragma unroll
    for (int j=0;j<4;j++){
      float4 iv = im[j*(HH/4)+c];
      acc[5+j] += tv.x*iv.x + tv.y*iv.y + tv.z*iv.z + tv.w*iv.w;
    }
  }
  __shared__ float red[9][4];
  int lane=threadIdx.x&31, w=threadIdx.x>>5;
  #pragma unroll
  for (int i=0;i<9;i++){
    float v=acc[i];
    for (int o=16;o>0;o>>=1) v += __shfl_down_sync(0xffffffffu,v,o);
    if (lane==0) red[i][w]=v;
  }
  __syncthreads();
  if (threadIdx.x==0){
    float tot[9];
    #pragma unroll
    for (int i=0;i<9;i++) tot[i]=red[i][0]+red[i][1]+red[i][2]+red[i][3];
    float tn = sqrtf(tot[0]);
    int amL=0; float mvL=3.4e38f;
    for (int j=0;j<4;j++){
      float den = fmaxf(tn*g_nrm[b*8+j], 1e-8f);
      float s = tot[1+j]/den;
      if (s<mvL){ mvL=s; amL=j; }
    }
    g_minL[bt]=amL;
    int amI=0; float mvI=3.4e38f;
    for (int j=0;j<4;j++){
      float den = fmaxf(tn*g_nrm[b*8+4+j], 1e-8f);
      float s = tot[5+j]/den;
      if (s<mvI){ mvI=s; amI=j; }
    }
    g_minI[bt]=amI;
  }
}

// ======================= HMMA GEMM (M128xN128, pure fp16, K-step 64, 12 stages) =======================
#define APAD 72
#define TILE_E (128*APAD)          /* 9216 halves = 18432 B */
#define BUF_E  (2*TILE_E)
#define NBUF 2
#define GEMM_SMEM (NBUF*BUF_E*2)   /* 73728 bytes */

__device__ __forceinline__ uint32_t smem_u32(const void* p){
  return (uint32_t)__cvta_generic_to_shared(p);
}
__device__ __forceinline__ void cp16(uint32_t dst, const void* src){
  asm volatile("cp.async.cg.shared.global [%0], [%1], 16;" :: "r"(dst), "l"(src));
}
__device__ __forceinline__ void cp_commit(){ asm volatile("cp.async.commit_group;"); }
__device__ __forceinline__ void cp_wait0(){ asm volatile("cp.async.wait_group 0;"); }
__device__ __forceinline__ void ldmx4(uint32_t a, uint32_t& r0, uint32_t& r1, uint32_t& r2, uint32_t& r3){
  asm volatile("ldmatrix.sync.aligned.m8n8.x4.shared.b16 {%0,%1,%2,%3}, [%4];"
    : "=r"(r0), "=r"(r1), "=r"(r2), "=r"(r3) : "r"(a));
}
__device__ __forceinline__ void mma16816(float* d, const uint32_t* a, uint32_t b0, uint32_t b1){
  asm volatile(
    "mma.sync.aligned.m16n8k16.row.col.f32.f16.f16.f32 "
    "{%0,%1,%2,%3}, {%4,%5,%6,%7}, {%8,%9}, {%0,%1,%2,%3};"
    : "+f"(d[0]), "+f"(d[1]), "+f"(d[2]), "+f"(d[3])
    : "r"(a[0]), "r"(a[1]), "r"(a[2]), "r"(a[3]), "r"(b0), "r"(b1));
}

__global__ void __launch_bounds__(256,2) k_gemm_mma(int layer,
    const float* __restrict__ asrc, const float* __restrict__ adst){
  extern __shared__ __half sm[];

  int tid = threadIdx.x;
  int wid = tid >> 5, lane = tid & 31;
  int wm = wid & 3, wn = wid >> 2;        // warp tile 32 rows x 64 cols
  int bx = blockIdx.x;                     // n tile 0..5
  int by = blockIdx.y;                     // m tile 0..64

  const __half* wH = g_wh + (size_t)layer*HH*HH;

  // loader mapping: 4 (row,chunk) pairs per tile per thread
  // idx = tid + i*256, i=0..3 : row = idx>>3 (0..127), chunk col = (idx&7)*8
  int lrow[4], lcol[4];
  int mAr[4], nBr[4];
  uint32_t dOf[4];
  #pragma unroll
  for (int i=0;i<4;i++){
    int idx = tid + i*256;
    int r = idx >> 3;
    int c = (idx & 7) * 8;
    lrow[i]=r; lcol[i]=c;
    int ma = by*128 + r; if (ma >= MROWS) ma = MROWS-1;
    mAr[i] = ma;
    nBr[i] = bx*128 + r;
    dOf[i] = (uint32_t)(r*APAD + c)*2;
  }
  uint32_t sBase = smem_u32(sm);

  uint32_t aRow = (uint32_t)(wm*32 + ((lane>>3)&1)*8 + (lane&7));
  uint32_t aCol = (uint32_t)(((lane>>4)&1)*8);
  uint32_t bRow = (uint32_t)(wn*64 + ((lane>>4)&1)*8 + (lane&7));
  uint32_t bCol = (uint32_t)(((lane>>3)&1)*8);

  float acc[2][8][4];
  #pragma unroll
  for (int i=0;i<2;i++)
    #pragma unroll
    for (int j=0;j<8;j++)
      #pragma unroll
      for (int k=0;k<4;k++) acc[i][j][k]=0.f;

  const int NSTAGE = 12;   // K-step 64
  auto issue = [&](int s){
    int k0 = s * 64;
    uint32_t off = sBase + (uint32_t)((s & 1) * BUF_E) * 2;
    #pragma unroll
    for (int i=0;i<4;i++)
      cp16(off + dOf[i], g_hh + (size_t)mAr[i]*HH + k0 + lcol[i]);
    #pragma unroll
    for (int i=0;i<4;i++)
      cp16(off + TILE_E*2 + dOf[i], wH + (size_t)nBr[i]*HH + k0 + lcol[i]);
    cp_commit();
  };

  issue(0);
  for (int s = 0; s < NSTAGE; s++){
    cp_wait0();              // stage s data complete
    __syncthreads();         // all warps done with stage s-1 buffer + see stage s data
    if (s+1 < NSTAGE) issue(s+1);   // other buffer: safe after sync
    uint32_t buf = sBase + (uint32_t)((s & 1) * BUF_E) * 2;
    uint32_t tA = buf, tB = buf + TILE_E*2;
    #pragma unroll
    for (int kk = 0; kk < 64; kk += 16){
      uint32_t a[2][4], b[4][4];
      #pragma unroll
      for (int mt=0; mt<2; mt++){
        uint32_t ro = ((aRow + mt*16)*APAD + aCol + kk)*2;
        ldmx4(tA + ro, a[mt][0], a[mt][1], a[mt][2], a[mt][3]);
      }
      #pragma unroll
      for (int nt=0; nt<4; nt++){
        uint32_t ro = ((bRow + nt*16)*APAD + bCol + kk)*2;
        ldmx4(tB + ro, b[nt][0], b[nt][1], b[nt][2], b[nt][3]);
      }
      #pragma unroll
      for (int mt=0; mt<2; mt++)
        #pragma unroll
        for (int n=0; n<8; n++){
          int nt = n >> 1, pr = n & 1;
          mma16816(acc[mt][n], a[mt], b[nt][pr*2], b[nt][pr*2+1]);
        }
    }
  }

  // epilogue 1: write accumulators to g_hw
  #pragma unroll
  for (int mt=0; mt<2; mt++){
    int rr = by*128 + wm*32 + mt*16 + (lane>>2);
    #pragma unroll
    for (int n=0; n<8; n++){
      int c0 = bx*128 + wn*64 + n*8 + (lane&3)*2;
      if (rr < MROWS)
        *(float2*)(g_hw + (size_t)rr*HH + c0) = make_float2(acc[mt][n][0], acc[mt][n][1]);
      if (rr+8 < MROWS)
        *(float2*)(g_hw + (size_t)(rr+8)*HH + c0) = make_float2(acc[mt][n][2], acc[mt][n][3]);
    }
  }

  // epilogue 2: fused es/ed reduction. This warp's 64 cols lie in one head.
  int head = (bx*128 + wn*64) / DH;
  #pragma unroll
  for (int mt=0; mt<2; mt++){
    float ses0=0.f, sed0=0.f, ses1=0.f, sed1=0.f;
    #pragma unroll
    for (int n=0; n<8; n++){
      int c = bx*128 + wn*64 + n*8 + (lane&3)*2;
      float a0=asrc[c], a1=asrc[c+1], dd0=adst[c], dd1=adst[c+1];
      ses0 += acc[mt][n][0]*a0 + acc[mt][n][1]*a1;
      sed0 += acc[mt][n][0]*dd0 + acc[mt][n][1]*dd1;
      ses1 += acc[mt][n][2]*a0 + acc[mt][n][3]*a1;
      sed1 += acc[mt][n][2]*dd0 + acc[mt][n][3]*dd1;
    }
    #pragma unroll
    for (int o=1; o<=2; o<<=1){
      ses0 += __shfl_xor_sync(0xffffffffu, ses0, o);
      sed0 += __shfl_xor_sync(0xffffffffu, sed0, o);
      ses1 += __shfl_xor_sync(0xffffffffu, ses1, o);
      sed1 += __shfl_xor_sync(0xffffffffu, sed1, o);
    }
    if ((lane&3)==0){
      int rr = by*128 + wm*32 + mt*16 + (lane>>2);
      if (rr < MROWS){
        atomicAdd(&g_es[rr*NHEAD+head], ses0);
        atomicAdd(&g_ed[rr*NHEAD+head], sed0);
      }
      if (rr+8 < MROWS){
        atomicAdd(&g_es[(rr+8)*NHEAD+head], ses1);
        atomicAdd(&g_ed[(rr+8)*NHEAD+head], sed1);
      }
    }
  }
}

// 8 static in-edges for big node j (0..3 = label j, 4..7 = image j-4)
__device__ __forceinline__ int static_src(int j,int s){
  if (j<LLn){
    if (s<4) return TT+LLn+s;
    if (s<7){ int p=s-4; if(p>=j)p++; return TT+p; }
    return TT+j;
  } else {
    int jj=j-LLn;
    if (s<4) return TT+s;
    if (s<7){ int p=s-4; if(p>=jj)p++; return TT+LLn+p; }
    return TT+LLn+jj;
  }
}

// ---------------- big-node softmax max & sumexp (and zero agg) ----------------
__global__ void k_ms(){
  int b = blockIdx.x>>3, j = blockIdx.x&7;
  int tid = threadIdx.x;
  int jj = (j<LLn)? j : j-LLn;
  int dst = (j<LLn)? (TT+j) : (TT+LLn+jj);
  for (int c=tid;c<HH;c+=256) g_agg[blockIdx.x*HH+c]=0.f;
  float edv[4];
  #pragma unroll
  for (int h=0;h<4;h++) edv[h]=g_ed[(size_t)(b*NN+dst)*NHEAD+h];
  const int* minA = (j<LLn)? (g_minL+b*TT) : (g_minI+b*TT);
  float mx[4]={-3.4e38f,-3.4e38f,-3.4e38f,-3.4e38f};
  for (int t=tid;t<TT;t+=256){
    if (minA[t]!=jj){
      const float* e = g_es + (size_t)(b*NN+t)*NHEAD;
      #pragma unroll
      for (int h=0;h<4;h++) mx[h]=fmaxf(mx[h], lrelu(e[h]+edv[h]));
    }
  }
  if (tid==0){
    #pragma unroll
    for (int s=0;s<8;s++){
      int sr = static_src(j,s);
      const float* e = g_es + (size_t)(b*NN+sr)*NHEAD;
      #pragma unroll
      for (int h=0;h<4;h++) mx[h]=fmaxf(mx[h], lrelu(e[h]+edv[h]));
    }
  }
  __shared__ float red[256][4];
  #pragma unroll
  for (int h=0;h<4;h++) red[tid][h]=mx[h];
  __syncthreads();
  for (int st=128;st>0;st>>=1){
    if (tid<st){
      #pragma unroll
      for (int h=0;h<4;h++) red[tid][h]=fmaxf(red[tid][h],red[tid+st][h]);
    }
    __syncthreads();
  }
  float mv[4];
  #pragma unroll
  for (int h=0;h<4;h++) mv[h]=red[0][h];
  __syncthreads();
  float sm[4]={0.f,0.f,0.f,0.f};
  for (int t=tid;t<TT;t+=256){
    if (minA[t]!=jj){
      const float* e = g_es + (size_t)(b*NN+t)*NHEAD;
      #pragma unroll
      for (int h=0;h<4;h++) sm[h] += __expf(lrelu(e[h]+edv[h])-mv[h]);
    }
  }
  if (tid==0){
    #pragma unroll
    for (int s=0;s<8;s++){
      int sr = static_src(j,s);
      const float* e = g_es + (size_t)(b*NN+sr)*NHEAD;
      #pragma unroll
      for (int h=0;h<4;h++) sm[h] += __expf(lrelu(e[h]+edv[h])-mv[h]);
    }
  }
  #pragma unroll
  for (int h=0;h<4;h++) red[tid][h]=sm[h];
  __syncthreads();
  for (int st=128;st>0;st>>=1){
    if (tid<st){
      #pragma unroll
      for (int h=0;h<4;h++) red[tid][h]+=red[tid+st][h];
    }
    __syncthreads();
  }
  if (tid<4){
    g_m[(b*8+j)*NHEAD+tid]=mv[tid];
    g_s[(b*8+j)*NHEAD+tid]=red[0][tid];
  }
}

// ---------------- big-node weighted aggregation (all 8 j per block, alpha inline) ----------------
__global__ void k_agg(){
  int b  = blockIdx.x >> 5;
  int sp = blockIdx.x & 31;
  int tid = threadIdx.x;
  int t0 = sp*32;
  __shared__ float sal[32][8][4];
  #pragma unroll
  for (int q=0;q<4;q++){
    int idx = tid + q*256;
    int tl = idx >> 5;
    int j  = (idx >> 2) & 7;
    int h  = idx & 3;
    int jj = (j<LLn)? j : j-LLn;
    int dst = (j<LLn)? (TT+j) : (TT+LLn+jj);
    int t = t0 + tl;
    int excl = (j<LLn)? (g_minL[b*TT+t]==jj) : (g_minI[b*TT+t]==jj);
    float al = 0.f;
    if (!excl){
      float e = lrelu(g_es[(size_t)(b*NN+t)*NHEAD+h] + g_ed[(size_t)(b*NN+dst)*NHEAD+h]);
      al = __expf(e - g_m[(b*8+j)*NHEAD+h]) / g_s[(b*8+j)*NHEAD+h];
    }
    sal[tl][j][h] = al;
  }
  __syncthreads();
  int c0=tid, c1=tid+256, c2=tid+512;
  int h0=c0/DH, h1=c1/DH, h2=c2/DH;
  float a0[8], a1[8], a2[8];
  #pragma unroll
  for (int j=0;j<8;j++){ a0[j]=0.f; a1[j]=0.f; a2[j]=0.f; }
  for (int tl=0; tl<32; tl++){
    const float* hr = g_hw + (size_t)(b*NN + t0+tl)*HH;
    float v0=hr[c0], v1=hr[c1], v2=hr[c2];
    #pragma unroll
    for (int j=0;j<8;j++){
      a0[j] += sal[tl][j][h0]*v0;
      a1[j] += sal[tl][j][h1]*v1;
      a2[j] += sal[tl][j][h2]*v2;
    }
  }
  #pragma unroll
  for (int j=0;j<8;j++){
    atomicAdd(&g_agg[(b*8+j)*HH+c0], a0[j]);
    atomicAdd(&g_agg[(b*8+j)*HH+c1], a1[j]);
    atomicAdd(&g_agg[(b*8+j)*HH+c2], a2[j]);
  }
}

// ---------------- big-node epilogue: static edges + bias+relu+residual+LN (+conv) ----------------
__global__ void k_big(const float* __restrict__ bias,const float* __restrict__ lng,
                      const float* __restrict__ lnb){
  int b = blockIdx.x>>3, j = blockIdx.x&7;
  int jj = (j<LLn)? j : j-LLn;
  int node = (j<LLn)? (TT+j) : (TT+LLn+jj);
  int tid = threadIdx.x;
  __shared__ float sal[8][4];
  __shared__ int ssrc[8];
  if (tid<32){
    int s=tid>>2, h=tid&3;
    int sr = static_src(j,s);
    if (h==0) ssrc[s]=sr;
    float e = lrelu(g_es[(size_t)(b*NN+sr)*NHEAD+h] + g_ed[(size_t)(b*NN+node)*NHEAD+h]);
    sal[s][h] = __expf(e - g_m[(b*8+j)*NHEAD+h]) / g_s[(b*8+j)*NHEAD+h];
  }
  __syncthreads();
  size_t row = (size_t)(b*NN+node)*HH;
  float v[3]; float s=0.f, sq=0.f;
  #pragma unroll
  for (int r=0;r<3;r++){
    int c = tid + 256*r;
    int hd = c/DH;
    float o = g_agg[(b*8+j)*HH+c];
    #pragma unroll
    for (int e=0;e<8;e++)
      o += sal[e][hd] * g_hw[(size_t)(b*NN+ssrc[e])*HH + c];
    o = fmaxf(o + bias[c], 0.f);
    float y = o + g_h[row+c];
    v[r]=y; s+=y; sq+=y*y;
  }
  __shared__ float rs[256], rq[256];
  rs[tid]=s; rq[tid]=sq; __syncthreads();
  for (int st=128;st>0;st>>=1){
    if (tid<st){ rs[tid]+=rs[tid+st]; rq[tid]+=rq[tid+st]; }
    __syncthreads();
  }
  float mu = rs[0]*(1.f/HH);
  float var = rq[0]*(1.f/HH) - mu*mu;
  float rstd = rsqrtf(var + 1e-5f);
  #pragma unroll
  for (int r=0;r<3;r++){
    int c = tid + 256*r;
    float y = (v[r]-mu)*rstd*lng[c] + lnb[c];
    g_h[row+c] = y;
    g_hh[row+c] = __float2half(y);
  }
}

// ---------------- text-node: full fused attention + epilogue (R6 proven) ----------------
__global__ void k_text(const float* __restrict__ bias,const float* __restrict__ lng,
                       const float* __restrict__ lnb, float* __restrict__ outp, int last){
  int bt = blockIdx.x;
  int b = bt/TT, t = bt%TT;
  int tid = threadIdx.x;
  __shared__ int ssrc[9];
  __shared__ int snum;
  __shared__ float sal[9][4];
  if (tid==0){
    int n=0;
    ssrc[n++]=t;
    if (t>0)    ssrc[n++]=t-1;
    if (t<TT-1) ssrc[n++]=t+1;
    int ml=g_minL[bt], mi=g_minI[bt];
    #pragma unroll
    for (int j2=0;j2<4;j2++) if (j2!=ml) ssrc[n++]=TT+j2;
    #pragma unroll
    for (int j2=0;j2<4;j2++) if (j2!=mi) ssrc[n++]=TT+LLn+j2;
    snum=n;
  }
  __syncthreads();
  int ns = snum;
  if (tid<4){
    float ed = g_ed[(size_t)(b*NN+t)*NHEAD + tid];
    float ev[9]; float mxv=-3.4e38f;
    for (int e=0;e<ns;e++){
      float x = lrelu(g_es[(size_t)(b*NN+ssrc[e])*NHEAD + tid] + ed);
      ev[e]=x; mxv=fmaxf(mxv,x);
    }
    float sm=0.f;
    for (int e=0;e<ns;e++){ float w=__expf(ev[e]-mxv); ev[e]=w; sm+=w; }
    float inv = 1.f/sm;
    for (int e=0;e<ns;e++) sal[e][tid]=ev[e]*inv;
  }
  __syncthreads();
  size_t row = (size_t)(b*NN+t)*HH;
  float v[3]; float s=0.f, sq=0.f;
  #pragma unroll
  for (int r=0;r<3;r++){
    int c = tid + 256*r;
    int hd = c/DH;
    float a = 0.f;
    for (int e=0;e<ns;e++)
      a += sal[e][hd] * g_hw[(size_t)(b*NN+ssrc[e])*HH + c];
    float o = fmaxf(a + bias[c], 0.f);
    float y = o + g_h[row+c];
    v[r]=y; s+=y; sq+=y*y;
  }
  __shared__ float rs[256], rq[256];
  rs[tid]=s; rq[tid]=sq; __syncthreads();
  for (int st=128;st>0;st>>=1){
    if (tid<st){ rs[tid]+=rs[tid+st]; rq[tid]+=rq[tid+st]; }
    __syncthreads();
  }
  float mu = rs[0]*(1.f/HH);
  float var = rq[0]*(1.f/HH) - mu*mu;
  float rstd = rsqrtf(var + 1e-5f);
  if (last){
    float* od = outp + ((size_t)b*TT + t)*HH;
    #pragma unroll
    for (int r=0;r<3;r++){
      int c = tid + 256*r;
      od[c] = (v[r]-mu)*rstd*lng[c] + lnb[c];
    }
  } else {
    #pragma unroll
    for (int r=0;r<3;r++){
      int c = tid + 256*r;
      float y = (v[r]-mu)*rstd*lng[c] + lnb[c];
      g_h[row+c] = y;
      g_hh[row+c] = __float2half(y);
    }
  }
}

extern "C" void kernel_launch(void* const* d_in, const int* in_sizes, int n_in,
                              void* d_out, int out_size) {
  const float* text = (const float*)d_in[0];
  const float* lab  = (const float*)d_in[1];
  const float* img  = (const float*)d_in[2];
  const float* W    = (const float*)d_in[3];
  const float* asrc = (const float*)d_in[4];
  const float* adst = (const float*)d_in[5];
  const float* bias = (const float*)d_in[6];
  const float* lng  = (const float*)d_in[7];
  const float* lnb  = (const float*)d_in[8];
  float* out = (float*)d_out;

  cudaFuncSetAttribute(k_gemm_mma, cudaFuncAttributeMaxDynamicSharedMemorySize, GEMM_SMEM);

  // launch order keeps the GEMM at profiled slot 4
  k_zero<<<(MROWS*NHEAD+255)/256, 256>>>();
  k_pack<<<(MROWS*HH+255)/256, 256>>>(text, lab, img);
  k_cvtW<<<dim3(24,24,3), dim3(32,32)>>>(W);
  k_gemm_mma<<<dim3(6,65), 256, GEMM_SMEM>>>(0, asrc, adst);
  k_norm<<<BB*8, 128>>>(lab, img);
  k_topk<<<BB*TT, 128>>>(text, lab, img);

  for (int l=0; l<NLAY; l++){
    int last = (l == NLAY-1);
    if (l > 0){
      k_zero<<<(MROWS*NHEAD+255)/256, 256>>>();
      k_gemm_mma<<<dim3(6,65), 256, GEMM_SMEM>>>(l, asrc + l*NHEAD*DH, adst + l*NHEAD*DH);
    }
    if (!last){
      k_ms<<<BB*8, 256>>>();
      k_agg<<<BB*32, 256>>>();
      k_big<<<BB*8, 256>>>(bias + l*HH, lng + l*HH, lnb + l*HH);
    }
    k_text<<<BB*TT, 256>>>(bias + l*HH, lng + l*HH, lnb + l*HH, out, last);
  }
}

// round 15
// speedup vs baseline: 1.2166x; 1.1563x over previous
#include <cuda_runtime.h>
#include <cuda_fp16.h>
#include <math.h>
#include <cstdint>

#define BB 8
#define TT 1024
#define LLn 4
#define IIn 4
#define HH 768
#define NHEAD 4
#define DH 192
#define NLAY 3
#define NN (TT+LLn+IIn)      /* 1032 */
#define MROWS (BB*NN)        /* 8256 */

__device__ float g_h [MROWS*HH];
__device__ float g_hw[MROWS*HH];
__device__ float g_es[MROWS*NHEAD];
__device__ float g_ed[MROWS*NHEAD];
__device__ int   g_minL[BB*TT];
__device__ int   g_minI[BB*TT];
__device__ float g_nrm[BB*8];
__device__ float g_m[BB*8*NHEAD];
__device__ float g_s[BB*8*NHEAD];
__device__ float g_agg[BB*8*HH];

// fp16 operands
__device__ __half g_hh[MROWS*HH];
__device__ __half g_wh[NLAY*HH*HH];   // transposed: [n][k]

__device__ __forceinline__ float lrelu(float x){ return x>0.f ? x : 0.2f*x; }

// ---------------- pack inputs into node state (+fp16) ----------------
__global__ void k_pack(const float* __restrict__ text,const float* __restrict__ lab,
                       const float* __restrict__ img){
  int idx = blockIdx.x*256 + threadIdx.x;
  if (idx >= MROWS*HH) return;
  int c = idx % HH;
  int n = (idx / HH) % NN;
  int b = idx / (NN*HH);
  float v;
  if (n < TT)            v = text[((size_t)b*TT + n)*HH + c];
  else if (n < TT+LLn)   v = lab [((size_t)b*LLn + (n-TT))*HH + c];
  else                   v = img [((size_t)b*IIn + (n-TT-LLn))*HH + c];
  g_h[idx] = v;
  g_hh[idx] = __float2half(v);
}

// ---------------- convert weights: transpose + fp16 (all layers) ----------------
__global__ void k_cvtW(const float* __restrict__ W){
  __shared__ float tile[32][33];
  int l = blockIdx.z;
  int n0 = blockIdx.x*32, k0 = blockIdx.y*32;
  const float* Wl = W + (size_t)l*HH*HH;
  tile[threadIdx.y][threadIdx.x] = Wl[(size_t)(k0+threadIdx.y)*HH + n0+threadIdx.x];
  __syncthreads();
  float x = tile[threadIdx.x][threadIdx.y];
  size_t o = (size_t)l*HH*HH + (size_t)(n0+threadIdx.y)*HH + (k0+threadIdx.x);
  g_wh[o] = __float2half(x);
}

// ---------------- zero es/ed before GEMM's fused atomic reduction ----------------
__global__ void k_zero(){
  int i = blockIdx.x*256 + threadIdx.x;
  if (i < MROWS*NHEAD){ g_es[i]=0.f; g_ed[i]=0.f; }
}

// ---------------- per-sample label/image norms ----------------
__global__ void k_norm(const float* __restrict__ lab,const float* __restrict__ img){
  int b = blockIdx.x / 8, j = blockIdx.x % 8;
  const float* row = (j<LLn) ? (lab + ((size_t)b*LLn + j)*HH)
                             : (img + ((size_t)b*IIn + (j-LLn))*HH);
  float s = 0.f;
  for (int c=threadIdx.x; c<HH; c+=128){ float v=row[c]; s += v*v; }
  __shared__ float red[128];
  red[threadIdx.x]=s; __syncthreads();
  for (int st=64; st>0; st>>=1){
    if (threadIdx.x<st) red[threadIdx.x]+=red[threadIdx.x+st];
    __syncthreads();
  }
  if (threadIdx.x==0) g_nrm[blockIdx.x] = sqrtf(red[0]);
}

// ---------------- top-k (store excluded argmin), float4 loads ----------------
__global__ void k_topk(const float* __restrict__ text,const float* __restrict__ lab,
                       const float* __restrict__ img){
  int bt = blockIdx.x;
  int b = bt / TT, t = bt % TT;
  const float4* trow = (const float4*)(text + ((size_t)b*TT + t)*HH);
  const float4* lb = (const float4*)(lab + (size_t)b*LLn*HH);
  const float4* im = (const float4*)(img + (size_t)b*IIn*HH);
  float acc[9];
  #pragma unroll
  for (int i=0;i<9;i++) acc[i]=0.f;
  for (int c=threadIdx.x; c<HH/4; c+=128){
    float4 tv = trow[c];
    acc[0] += tv.x*tv.x + tv.y*tv.y + tv.z*tv.z + tv.w*tv.w;
    #pragma unroll
    for (int j=0;j<4;j++){
      float4 lv = lb[j*(HH/4)+c];
      acc[1+j] += tv.x*lv.x + tv.y*lv.y + tv.z*lv.z + tv.w*lv.w;
    }
    #pragma unroll
    for (int j=0;j<4;j++){
      float4 iv = im[j*(HH/4)+c];
      acc[5+j] += tv.x*iv.x + tv.y*iv.y + tv.z*iv.z + tv.w*iv.w;
    }
  }
  __shared__ float red[9][4];
  int lane=threadIdx.x&31, w=threadIdx.x>>5;
  #pragma unroll
  for (int i=0;i<9;i++){
    float v=acc[i];
    for (int o=16;o>0;o>>=1) v += __shfl_down_sync(0xffffffffu,v,o);
    if (lane==0) red[i][w]=v;
  }
  __syncthreads();
  if (threadIdx.x==0){
    float tot[9];
    #pragma unroll
    for (int i=0;i<9;i++) tot[i]=red[i][0]+red[i][1]+red[i][2]+red[i][3];
    float tn = sqrtf(tot[0]);
    int amL=0; float mvL=3.4e38f;
    for (int j=0;j<4;j++){
      float den = fmaxf(tn*g_nrm[b*8+j], 1e-8f);
      float s = tot[1+j]/den;
      if (s<mvL){ mvL=s; amL=j; }
    }
    g_minL[bt]=amL;
    int amI=0; float mvI=3.4e38f;
    for (int j=0;j<4;j++){
      float den = fmaxf(tn*g_nrm[b*8+4+j], 1e-8f);
      float s = tot[5+j]/den;
      if (s<mvI){ mvI=s; amI=j; }
    }
    g_minI[bt]=amI;
  }
}

// ======================= HMMA GEMM (M128xN128, pure fp16, K-step 64, 12 stages) =======================
#define APAD 72
#define TILE_E (128*APAD)
#define BUF_E  (2*TILE_E)
#define NBUF 2
#define GEMM_SMEM (NBUF*BUF_E*2)   /* 73728 bytes */

__device__ __forceinline__ uint32_t smem_u32(const void* p){
  return (uint32_t)__cvta_generic_to_shared(p);
}
__device__ __forceinline__ void cp16(uint32_t dst, const void* src){
  asm volatile("cp.async.cg.shared.global [%0], [%1], 16;" :: "r"(dst), "l"(src));
}
__device__ __forceinline__ void cp_commit(){ asm volatile("cp.async.commit_group;"); }
__device__ __forceinline__ void cp_wait0(){ asm volatile("cp.async.wait_group 0;"); }
__device__ __forceinline__ void ldmx4(uint32_t a, uint32_t& r0, uint32_t& r1, uint32_t& r2, uint32_t& r3){
  asm volatile("ldmatrix.sync.aligned.m8n8.x4.shared.b16 {%0,%1,%2,%3}, [%4];"
    : "=r"(r0), "=r"(r1), "=r"(r2), "=r"(r3) : "r"(a));
}
__device__ __forceinline__ void mma16816(float* d, const uint32_t* a, uint32_t b0, uint32_t b1){
  asm volatile(
    "mma.sync.aligned.m16n8k16.row.col.f32.f16.f16.f32 "
    "{%0,%1,%2,%3}, {%4,%5,%6,%7}, {%8,%9}, {%0,%1,%2,%3};"
    : "+f"(d[0]), "+f"(d[1]), "+f"(d[2]), "+f"(d[3])
    : "r"(a[0]), "r"(a[1]), "r"(a[2]), "r"(a[3]), "r"(b0), "r"(b1));
}

__global__ void __launch_bounds__(256,2) k_gemm_mma(int layer,
    const float* __restrict__ asrc, const float* __restrict__ adst){
  extern __shared__ __half sm[];

  int tid = threadIdx.x;
  int wid = tid >> 5, lane = tid & 31;
  int wm = wid & 3, wn = wid >> 2;        // warp tile 32 rows x 64 cols
  int bx = blockIdx.x;                     // n tile 0..5
  int by = blockIdx.y;                     // m tile 0..64

  const __half* wH = g_wh + (size_t)layer*HH*HH;

  int lrow[4], lcol[4];
  int mAr[4], nBr[4];
  uint32_t dOf[4];
  #pragma unroll
  for (int i=0;i<4;i++){
    int idx = tid + i*256;
    int r = idx >> 3;
    int c = (idx & 7) * 8;
    lrow[i]=r; lcol[i]=c;
    int ma = by*128 + r; if (ma >= MROWS) ma = MROWS-1;
    mAr[i] = ma;
    nBr[i] = bx*128 + r;
    dOf[i] = (uint32_t)(r*APAD + c)*2;
  }
  uint32_t sBase = smem_u32(sm);

  uint32_t aRow = (uint32_t)(wm*32 + ((lane>>3)&1)*8 + (lane&7));
  uint32_t aCol = (uint32_t)(((lane>>4)&1)*8);
  uint32_t bRow = (uint32_t)(wn*64 + ((lane>>4)&1)*8 + (lane&7));
  uint32_t bCol = (uint32_t)(((lane>>3)&1)*8);

  float acc[2][8][4];
  #pragma unroll
  for (int i=0;i<2;i++)
    #pragma unroll
    for (int j=0;j<8;j++)
      #pragma unroll
      for (int k=0;k<4;k++) acc[i][j][k]=0.f;

  const int NSTAGE = 12;   // K-step 64
  auto issue = [&](int s){
    int k0 = s * 64;
    uint32_t off = sBase + (uint32_t)((s & 1) * BUF_E) * 2;
    #pragma unroll
    for (int i=0;i<4;i++)
      cp16(off + dOf[i], g_hh + (size_t)mAr[i]*HH + k0 + lcol[i]);
    #pragma unroll
    for (int i=0;i<4;i++)
      cp16(off + TILE_E*2 + dOf[i], wH + (size_t)nBr[i]*HH + k0 + lcol[i]);
    cp_commit();
  };

  issue(0);
  for (int s = 0; s < NSTAGE; s++){
    cp_wait0();
    __syncthreads();
    if (s+1 < NSTAGE) issue(s+1);
    uint32_t buf = sBase + (uint32_t)((s & 1) * BUF_E) * 2;
    uint32_t tA = buf, tB = buf + TILE_E*2;
    #pragma unroll
    for (int kk = 0; kk < 64; kk += 16){
      uint32_t a[2][4], b[4][4];
      #pragma unroll
      for (int mt=0; mt<2; mt++){
        uint32_t ro = ((aRow + mt*16)*APAD + aCol + kk)*2;
        ldmx4(tA + ro, a[mt][0], a[mt][1], a[mt][2], a[mt][3]);
      }
      #pragma unroll
      for (int nt=0; nt<4; nt++){
        uint32_t ro = ((bRow + nt*16)*APAD + bCol + kk)*2;
        ldmx4(tB + ro, b[nt][0], b[nt][1], b[nt][2], b[nt][3]);
      }
      #pragma unroll
      for (int mt=0; mt<2; mt++)
        #pragma unroll
        for (int n=0; n<8; n++){
          int nt = n >> 1, pr = n & 1;
          mma16816(acc[mt][n], a[mt], b[nt][pr*2], b[nt][pr*2+1]);
        }
    }
  }

  // epilogue 1: write accumulators to g_hw
  #pragma unroll
  for (int mt=0; mt<2; mt++){
    int rr = by*128 + wm*32 + mt*16 + (lane>>2);
    #pragma unroll
    for (int n=0; n<8; n++){
      int c0 = bx*128 + wn*64 + n*8 + (lane&3)*2;
      if (rr < MROWS)
        *(float2*)(g_hw + (size_t)rr*HH + c0) = make_float2(acc[mt][n][0], acc[mt][n][1]);
      if (rr+8 < MROWS)
        *(float2*)(g_hw + (size_t)(rr+8)*HH + c0) = make_float2(acc[mt][n][2], acc[mt][n][3]);
    }
  }

  // epilogue 2: fused es/ed reduction
  int head = (bx*128 + wn*64) / DH;
  #pragma unroll
  for (int mt=0; mt<2; mt++){
    float ses0=0.f, sed0=0.f, ses1=0.f, sed1=0.f;
    #pragma unroll
    for (int n=0; n<8; n++){
      int c = bx*128 + wn*64 + n*8 + (lane&3)*2;
      float a0=asrc[c], a1=asrc[c+1], dd0=adst[c], dd1=adst[c+1];
      ses0 += acc[mt][n][0]*a0 + acc[mt][n][1]*a1;
      sed0 += acc[mt][n][0]*dd0 + acc[mt][n][1]*dd1;
      ses1 += acc[mt][n][2]*a0 + acc[mt][n][3]*a1;
      sed1 += acc[mt][n][2]*dd0 + acc[mt][n][3]*dd1;
    }
    #pragma unroll
    for (int o=1; o<=2; o<<=1){
      ses0 += __shfl_xor_sync(0xffffffffu, ses0, o);
      sed0 += __shfl_xor_sync(0xffffffffu, sed0, o);
      ses1 += __shfl_xor_sync(0xffffffffu, ses1, o);
      sed1 += __shfl_xor_sync(0xffffffffu, sed1, o);
    }
    if ((lane&3)==0){
      int rr = by*128 + wm*32 + mt*16 + (lane>>2);
      if (rr < MROWS){
        atomicAdd(&g_es[rr*NHEAD+head], ses0);
        atomicAdd(&g_ed[rr*NHEAD+head], sed0);
      }
      if (rr+8 < MROWS){
        atomicAdd(&g_es[(rr+8)*NHEAD+head], ses1);
        atomicAdd(&g_ed[(rr+8)*NHEAD+head], sed1);
      }
    }
  }
}

// 8 static in-edges for big node j (0..3 = label j, 4..7 = image j-4)
__device__ __forceinline__ int static_src(int j,int s){
  if (j<LLn){
    if (s<4) return TT+LLn+s;
    if (s<7){ int p=s-4; if(p>=j)p++; return TT+p; }
    return TT+j;
  } else {
    int jj=j-LLn;
    if (s<4) return TT+s;
    if (s<7){ int p=s-4; if(p>=jj)p++; return TT+LLn+p; }
    return TT+LLn+jj;
  }
}

// ---------------- big-node softmax max & sumexp (and zero agg) ----------------
__global__ void k_ms(){
  int b = blockIdx.x>>3, j = blockIdx.x&7;
  int tid = threadIdx.x;
  int jj = (j<LLn)? j : j-LLn;
  int dst = (j<LLn)? (TT+j) : (TT+LLn+jj);
  for (int c=tid;c<HH;c+=256) g_agg[blockIdx.x*HH+c]=0.f;
  float edv[4];
  #pragma unroll
  for (int h=0;h<4;h++) edv[h]=g_ed[(size_t)(b*NN+dst)*NHEAD+h];
  const int* minA = (j<LLn)? (g_minL+b*TT) : (g_minI+b*TT);
  float mx[4]={-3.4e38f,-3.4e38f,-3.4e38f,-3.4e38f};
  for (int t=tid;t<TT;t+=256){
    if (minA[t]!=jj){
      const float* e = g_es + (size_t)(b*NN+t)*NHEAD;
      #pragma unroll
      for (int h=0;h<4;h++) mx[h]=fmaxf(mx[h], lrelu(e[h]+edv[h]));
    }
  }
  if (tid==0){
    #pragma unroll
    for (int s=0;s<8;s++){
      int sr = static_src(j,s);
      const float* e = g_es + (size_t)(b*NN+sr)*NHEAD;
      #pragma unroll
      for (int h=0;h<4;h++) mx[h]=fmaxf(mx[h], lrelu(e[h]+edv[h]));
    }
  }
  __shared__ float red[256][4];
  #pragma unroll
  for (int h=0;h<4;h++) red[tid][h]=mx[h];
  __syncthreads();
  for (int st=128;st>0;st>>=1){
    if (tid<st){
      #pragma unroll
      for (int h=0;h<4;h++) red[tid][h]=fmaxf(red[tid][h],red[tid+st][h]);
    }
    __syncthreads();
  }
  float mv[4];
  #pragma unroll
  for (int h=0;h<4;h++) mv[h]=red[0][h];
  __syncthreads();
  float sm[4]={0.f,0.f,0.f,0.f};
  for (int t=tid;t<TT;t+=256){
    if (minA[t]!=jj){
      const float* e = g_es + (size_t)(b*NN+t)*NHEAD;
      #pragma unroll
      for (int h=0;h<4;h++) sm[h] += __expf(lrelu(e[h]+edv[h])-mv[h]);
    }
  }
  if (tid==0){
    #pragma unroll
    for (int s=0;s<8;s++){
      int sr = static_src(j,s);
      const float* e = g_es + (size_t)(b*NN+sr)*NHEAD;
      #pragma unroll
      for (int h=0;h<4;h++) sm[h] += __expf(lrelu(e[h]+edv[h])-mv[h]);
    }
  }
  #pragma unroll
  for (int h=0;h<4;h++) red[tid][h]=sm[h];
  __syncthreads();
  for (int st=128;st>0;st>>=1){
    if (tid<st){
      #pragma unroll
      for (int h=0;h<4;h++) red[tid][h]+=red[tid+st][h];
    }
    __syncthreads();
  }
  if (tid<4){
    g_m[(b*8+j)*NHEAD+tid]=mv[tid];
    g_s[(b*8+j)*NHEAD+tid]=red[0][tid];
  }
}

// ---------------- big-node weighted aggregation (all 8 j per block, alpha inline) ----------------
__global__ void k_agg(){
  int b  = blockIdx.x >> 5;
  int sp = blockIdx.x & 31;
  int tid = threadIdx.x;
  int t0 = sp*32;
  __shared__ float sal[32][8][4];
  #pragma unroll
  for (int q=0;q<4;q++){
    int idx = tid + q*256;
    int tl = idx >> 5;
    int j  = (idx >> 2) & 7;
    int h  = idx & 3;
    int jj = (j<LLn)? j : j-LLn;
    int dst = (j<LLn)? (TT+j) : (TT+LLn+jj);
    int t = t0 + tl;
    int excl = (j<LLn)? (g_minL[b*TT+t]==jj) : (g_minI[b*TT+t]==jj);
    float al = 0.f;
    if (!excl){
      float e = lrelu(g_es[(size_t)(b*NN+t)*NHEAD+h] + g_ed[(size_t)(b*NN+dst)*NHEAD+h]);
      al = __expf(e - g_m[(b*8+j)*NHEAD+h]) / g_s[(b*8+j)*NHEAD+h];
    }
    sal[tl][j][h] = al;
  }
  __syncthreads();
  int c0=tid, c1=tid+256, c2=tid+512;
  int h0=c0/DH, h1=c1/DH, h2=c2/DH;
  float a0[8], a1[8], a2[8];
  #pragma unroll
  for (int j=0;j<8;j++){ a0[j]=0.f; a1[j]=0.f; a2[j]=0.f; }
  for (int tl=0; tl<32; tl++){
    const float* hr = g_hw + (size_t)(b*NN + t0+tl)*HH;
    float v0=hr[c0], v1=hr[c1], v2=hr[c2];
    #pragma unroll
    for (int j=0;j<8;j++){
      a0[j] += sal[tl][j][h0]*v0;
      a1[j] += sal[tl][j][h1]*v1;
      a2[j] += sal[tl][j][h2]*v2;
    }
  }
  #pragma unroll
  for (int j=0;j<8;j++){
    atomicAdd(&g_agg[(b*8+j)*HH+c0], a0[j]);
    atomicAdd(&g_agg[(b*8+j)*HH+c1], a1[j]);
    atomicAdd(&g_agg[(b*8+j)*HH+c2], a2[j]);
  }
}

// ---------------- big-node epilogue: static edges + bias+relu+residual+LN (+conv) ----------------
__global__ void k_big(const float* __restrict__ bias,const float* __restrict__ lng,
                      const float* __restrict__ lnb){
  int b = blockIdx.x>>3, j = blockIdx.x&7;
  int jj = (j<LLn)? j : j-LLn;
  int node = (j<LLn)? (TT+j) : (TT+LLn+jj);
  int tid = threadIdx.x;
  __shared__ float sal[8][4];
  __shared__ int ssrc[8];
  if (tid<32){
    int s=tid>>2, h=tid&3;
    int sr = static_src(j,s);
    if (h==0) ssrc[s]=sr;
    float e = lrelu(g_es[(size_t)(b*NN+sr)*NHEAD+h] + g_ed[(size_t)(b*NN+node)*NHEAD+h]);
    sal[s][h] = __expf(e - g_m[(b*8+j)*NHEAD+h]) / g_s[(b*8+j)*NHEAD+h];
  }
  __syncthreads();
  size_t row = (size_t)(b*NN+node)*HH;
  float v[3]; float s=0.f, sq=0.f;
  #pragma unroll
  for (int r=0;r<3;r++){
    int c = tid + 256*r;
    int hd = c/DH;
    float o = g_agg[(b*8+j)*HH+c];
    #pragma unroll
    for (int e=0;e<8;e++)
      o += sal[e][hd] * g_hw[(size_t)(b*NN+ssrc[e])*HH + c];
    o = fmaxf(o + bias[c], 0.f);
    float y = o + g_h[row+c];
    v[r]=y; s+=y; sq+=y*y;
  }
  __shared__ float rs[256], rq[256];
  rs[tid]=s; rq[tid]=sq; __syncthreads();
  for (int st=128;st>0;st>>=1){
    if (tid<st){ rs[tid]+=rs[tid+st]; rq[tid]+=rq[tid+st]; }
    __syncthreads();
  }
  float mu = rs[0]*(1.f/HH);
  float var = rq[0]*(1.f/HH) - mu*mu;
  float rstd = rsqrtf(var + 1e-5f);
  #pragma unroll
  for (int r=0;r<3;r++){
    int c = tid + 256*r;
    float y = (v[r]-mu)*rstd*lng[c] + lnb[c];
    g_h[row+c] = y;
    g_hh[row+c] = __float2half(y);
  }
}

// ---------------- text-node: block = (b, 8 tokens); big rows staged in 24KB SMEM ----------------
__global__ void __launch_bounds__(256) k_text(const float* __restrict__ bias,
                       const float* __restrict__ lng, const float* __restrict__ lnb,
                       float* __restrict__ outp, int last){
  __shared__ float sbig[8*HH];            // 24 KB: label rows 0-3, image rows 4-7
  __shared__ float salc[8][3][4];
  __shared__ float salb[8][6][4];
  int blk = blockIdx.x;
  int b = blk >> 7;
  int t0 = (blk & 127) * 8;
  int tid = threadIdx.x;
  int w = tid >> 5, lane = tid & 31;
  const float4* hw4 = (const float4*)(g_hw + (size_t)b*NN*HH);

  // stage 8 big rows (node TT+r, r=0..7): 8*192 float4
  for (int i = tid; i < 8*(HH/4); i += 256){
    int r = i / (HH/4), c4 = i % (HH/4);
    ((float4*)sbig)[i] = hw4[(size_t)(TT + r)*(HH/4) + c4];
  }
  __syncthreads();

  int t = t0 + w;
  int bt = b*TT + t;
  // edge lists (uniform across lanes of the warp)
  int csrc[3]; int ncs = 0;
  csrc[ncs++] = t;
  if (t > 0)    csrc[ncs++] = t-1;
  if (t < TT-1) csrc[ncs++] = t+1;
  int ml = g_minL[bt], mi = g_minI[bt];
  int bsrc[6]; int nbs = 0;
  #pragma unroll
  for (int j=0;j<4;j++) if (j != ml) bsrc[nbs++] = j;
  #pragma unroll
  for (int j=0;j<4;j++) if (j != mi) bsrc[nbs++] = 4+j;

  if (lane < 4){
    float ed = g_ed[(size_t)(b*NN+t)*NHEAD + lane];
    float ev[9]; float mx = -3.4e38f;
    for (int e=0;e<ncs;e++){
      float x = lrelu(g_es[(size_t)(b*NN+csrc[e])*NHEAD + lane] + ed);
      ev[e]=x; mx=fmaxf(mx,x);
    }
    for (int e=0;e<nbs;e++){
      float x = lrelu(g_es[(size_t)(b*NN+TT+bsrc[e])*NHEAD + lane] + ed);
      ev[ncs+e]=x; mx=fmaxf(mx,x);
    }
    float sm=0.f;
    int ns = ncs + nbs;
    for (int e=0;e<ns;e++){ float wv=__expf(ev[e]-mx); ev[e]=wv; sm+=wv; }
    float inv = 1.f/sm;
    for (int e=0;e<ncs;e++) salc[w][e][lane] = ev[e]*inv;
    for (int e=0;e<nbs;e++) salb[w][e][lane] = ev[ncs+e]*inv;
  }
  __syncwarp();

  size_t row = (size_t)(b*NN+t)*HH;
  const float4* gh4 = (const float4*)(g_h + row);
  const float4* bias4 = (const float4*)bias;
  const float4* sbig4 = (const float4*)sbig;
  float4 v[6]; float s=0.f, sq=0.f;
  #pragma unroll
  for (int i=0;i<6;i++){
    int c4 = lane + i*32;
    int hd = c4 / 48;       // 48 float4 per head
    float4 a = make_float4(0.f,0.f,0.f,0.f);
    for (int e=0;e<ncs;e++){
      float wv = salc[w][e][hd];
      float4 p = hw4[(size_t)csrc[e]*(HH/4) + c4];
      a.x += wv*p.x; a.y += wv*p.y; a.z += wv*p.z; a.w += wv*p.w;
    }
    for (int e=0;e<nbs;e++){
      float wv = salb[w][e][hd];
      float4 p = sbig4[bsrc[e]*(HH/4) + c4];
      a.x += wv*p.x; a.y += wv*p.y; a.z += wv*p.z; a.w += wv*p.w;
    }
    float4 bb = bias4[c4];
    float4 hh = gh4[c4];
    float4 y;
    y.x = fmaxf(a.x + bb.x, 0.f) + hh.x;
    y.y = fmaxf(a.y + bb.y, 0.f) + hh.y;
    y.z = fmaxf(a.z + bb.z, 0.f) + hh.z;
    y.w = fmaxf(a.w + bb.w, 0.f) + hh.w;
    v[i] = y;
    s  += y.x + y.y + y.z + y.w;
    sq += y.x*y.x + y.y*y.y + y.z*y.z + y.w*y.w;
  }
  #pragma unroll
  for (int o=16;o>0;o>>=1){
    s  += __shfl_xor_sync(0xffffffffu, s, o);
    sq += __shfl_xor_sync(0xffffffffu, sq, o);
  }
  float mu = s*(1.f/HH);
  float var = sq*(1.f/HH) - mu*mu;
  float rstd = rsqrtf(var + 1e-5f);
  const float4* lng4 = (const float4*)lng;
  const float4* lnb4 = (const float4*)lnb;
  if (last){
    float4* od = (float4*)(outp + ((size_t)bt)*HH);
    #pragma unroll
    for (int i=0;i<6;i++){
      int c4 = lane + i*32;
      float4 g = lng4[c4], bb = lnb4[c4];
      float4 y;
      y.x = (v[i].x-mu)*rstd*g.x + bb.x;
      y.y = (v[i].y-mu)*rstd*g.y + bb.y;
      y.z = (v[i].z-mu)*rstd*g.z + bb.z;
      y.w = (v[i].w-mu)*rstd*g.w + bb.w;
      od[c4] = y;
    }
  } else {
    float4* gh4w = (float4*)(g_h + row);
    uint2* hh2 = (uint2*)(g_hh + row);
    #pragma unroll
    for (int i=0;i<6;i++){
      int c4 = lane + i*32;
      float4 g = lng4[c4], bb = lnb4[c4];
      float4 y;
      y.x = (v[i].x-mu)*rstd*g.x + bb.x;
      y.y = (v[i].y-mu)*rstd*g.y + bb.y;
      y.z = (v[i].z-mu)*rstd*g.z + bb.z;
      y.w = (v[i].w-mu)*rstd*g.w + bb.w;
      gh4w[c4] = y;
      __half2 lo = __floats2half2_rn(y.x, y.y);
      __half2 hi = __floats2half2_rn(y.z, y.w);
      uint2 pk;
      pk.x = *(uint32_t*)&lo;
      pk.y = *(uint32_t*)&hi;
      hh2[c4] = pk;
    }
  }
}

extern "C" void kernel_launch(void* const* d_in, const int* in_sizes, int n_in,
                              void* d_out, int out_size) {
  const float* text = (const float*)d_in[0];
  const float* lab  = (const float*)d_in[1];
  const float* img  = (const float*)d_in[2];
  const float* W    = (const float*)d_in[3];
  const float* asrc = (const float*)d_in[4];
  const float* adst = (const float*)d_in[5];
  const float* bias = (const float*)d_in[6];
  const float* lng  = (const float*)d_in[7];
  const float* lnb  = (const float*)d_in[8];
  float* out = (float*)d_out;

  cudaFuncSetAttribute(k_gemm_mma, cudaFuncAttributeMaxDynamicSharedMemorySize, GEMM_SMEM);

  // launch order keeps the GEMM at profiled slot 4
  k_zero<<<(MROWS*NHEAD+255)/256, 256>>>();
  k_pack<<<(MROWS*HH+255)/256, 256>>>(text, lab, img);
  k_cvtW<<<dim3(24,24,3), dim3(32,32)>>>(W);
  k_gemm_mma<<<dim3(6,65), 256, GEMM_SMEM>>>(0, asrc, adst);
  k_norm<<<BB*8, 128>>>(lab, img);
  k_topk<<<BB*TT, 128>>>(text, lab, img);

  for (int l=0; l<NLAY; l++){
    int last = (l == NLAY-1);
    if (l > 0){
      k_zero<<<(MROWS*NHEAD+255)/256, 256>>>();
      k_gemm_mma<<<dim3(6,65), 256, GEMM_SMEM>>>(l, asrc + l*NHEAD*DH, adst + l*NHEAD*DH);
    }
    if (!last){
      k_ms<<<BB*8, 256>>>();
      k_agg<<<BB*32, 256>>>();
      k_big<<<BB*8, 256>>>(bias + l*HH, lng + l*HH, lnb + l*HH);
    }
    k_text<<<BB*128, 256>>>(bias + l*HH, lng + l*HH, lnb + l*HH, out, last);
  }
}

// round 16
// speedup vs baseline: 1.2675x; 1.0418x over previous
#include <cuda_runtime.h>
#include <cuda_fp16.h>
#include <math.h>
#include <cstdint>

#define BB 8
#define TT 1024
#define LLn 4
#define IIn 4
#define HH 768
#define NHEAD 4
#define DH 192
#define NLAY 3
#define NN (TT+LLn+IIn)      /* 1032 */
#define MROWS (BB*NN)        /* 8256 */

__device__ float g_h [MROWS*HH];
__device__ float g_hw[MROWS*HH];
__device__ float g_es[MROWS*NHEAD];
__device__ float g_ed[MROWS*NHEAD];
__device__ int   g_minL[BB*TT];
__device__ int   g_minI[BB*TT];
__device__ float g_nrm[BB*8];
__device__ float g_m[BB*8*NHEAD];
__device__ float g_s[BB*8*NHEAD];
__device__ float g_agg[BB*8*HH];

// fp16 operands
__device__ __half g_hh[MROWS*HH];
__device__ __half g_wh[NLAY*HH*HH];   // transposed: [n][k]

__device__ __forceinline__ float lrelu(float x){ return x>0.f ? x : 0.2f*x; }

// ---------------- pack inputs into node state (+fp16, +es/ed zero), float4 ----------------
__global__ void k_pack(const float* __restrict__ text,const float* __restrict__ lab,
                       const float* __restrict__ img){
  int idx = blockIdx.x*256 + threadIdx.x;
  if (idx >= MROWS*(HH/4)) return;
  int c4 = idx % (HH/4);
  int n = (idx / (HH/4)) % NN;
  int b = idx / ((HH/4)*NN);
  float4 v;
  if (n < TT)            v = ((const float4*)text)[((size_t)b*TT + n)*(HH/4) + c4];
  else if (n < TT+LLn)   v = ((const float4*)lab )[((size_t)b*LLn + (n-TT))*(HH/4) + c4];
  else                   v = ((const float4*)img )[((size_t)b*IIn + (n-TT-LLn))*(HH/4) + c4];
  ((float4*)g_h)[idx] = v;
  __half2 lo = __floats2half2_rn(v.x, v.y);
  __half2 hi = __floats2half2_rn(v.z, v.w);
  uint2 pk; pk.x = *(uint32_t*)&lo; pk.y = *(uint32_t*)&hi;
  ((uint2*)g_hh)[idx] = pk;
  if (idx < MROWS*NHEAD/4){
    float4 z = make_float4(0.f,0.f,0.f,0.f);
    ((float4*)g_es)[idx] = z;
    ((float4*)g_ed)[idx] = z;
  }
}

// ---------------- convert weights: transpose + fp16 (all layers) ----------------
__global__ void k_cvtW(const float* __restrict__ W){
  __shared__ float tile[32][33];
  int l = blockIdx.z;
  int n0 = blockIdx.x*32, k0 = blockIdx.y*32;
  const float* Wl = W + (size_t)l*HH*HH;
  tile[threadIdx.y][threadIdx.x] = Wl[(size_t)(k0+threadIdx.y)*HH + n0+threadIdx.x];
  __syncthreads();
  float x = tile[threadIdx.x][threadIdx.y];
  size_t o = (size_t)l*HH*HH + (size_t)(n0+threadIdx.y)*HH + (k0+threadIdx.x);
  g_wh[o] = __float2half(x);
}

// ---------------- zero es/ed before GEMM's fused atomic reduction (layers > 0) ----------------
__global__ void k_zero(){
  int i = blockIdx.x*256 + threadIdx.x;
  if (i < MROWS*NHEAD){ g_es[i]=0.f; g_ed[i]=0.f; }
}

// ---------------- per-sample label/image norms ----------------
__global__ void k_norm(const float* __restrict__ lab,const float* __restrict__ img){
  int b = blockIdx.x / 8, j = blockIdx.x % 8;
  const float* row = (j<LLn) ? (lab + ((size_t)b*LLn + j)*HH)
                             : (img + ((size_t)b*IIn + (j-LLn))*HH);
  float s = 0.f;
  for (int c=threadIdx.x; c<HH; c+=128){ float v=row[c]; s += v*v; }
  __shared__ float red[128];
  red[threadIdx.x]=s; __syncthreads();
  for (int st=64; st>0; st>>=1){
    if (threadIdx.x<st) red[threadIdx.x]+=red[threadIdx.x+st];
    __syncthreads();
  }
  if (threadIdx.x==0) g_nrm[blockIdx.x] = sqrtf(red[0]);
}

// ---------------- top-k: block = (b, 32 tokens), staged label/image rows ----------------
__global__ void __launch_bounds__(256) k_topk(const float* __restrict__ text,
                       const float* __restrict__ lab,const float* __restrict__ img){
  __shared__ float sbig[8*HH];    // 24 KB
  __shared__ float snrm[8];
  int blk = blockIdx.x;
  int b = blk >> 5;
  int t0 = (blk & 31) * 32;
  int tid = threadIdx.x, w = tid>>5, lane = tid&31;
  const float4* lb4 = (const float4*)(lab + (size_t)b*LLn*HH);
  const float4* im4 = (const float4*)(img + (size_t)b*IIn*HH);
  for (int i = tid; i < 8*(HH/4); i += 256){
    int r = i / (HH/4), c4 = i % (HH/4);
    ((float4*)sbig)[i] = (r < 4) ? lb4[r*(HH/4)+c4] : im4[(r-4)*(HH/4)+c4];
  }
  if (tid < 8) snrm[tid] = g_nrm[b*8+tid];
  __syncthreads();
  const float4* sbig4 = (const float4*)sbig;
  #pragma unroll
  for (int q=0; q<4; q++){
    int t = t0 + q*8 + w;
    int bt = b*TT + t;
    const float4* trow = (const float4*)(text + ((size_t)bt)*HH);
    float acc[9];
    #pragma unroll
    for (int i=0;i<9;i++) acc[i]=0.f;
    #pragma unroll
    for (int i=0;i<6;i++){
      int c4 = lane + i*32;
      float4 tv = trow[c4];
      acc[0] += tv.x*tv.x + tv.y*tv.y + tv.z*tv.z + tv.w*tv.w;
      #pragma unroll
      for (int j=0;j<8;j++){
        float4 lv = sbig4[j*(HH/4) + c4];
        acc[1+j] += tv.x*lv.x + tv.y*lv.y + tv.z*lv.z + tv.w*lv.w;
      }
    }
    #pragma unroll
    for (int o=16;o>0;o>>=1){
      #pragma unroll
      for (int i=0;i<9;i++) acc[i] += __shfl_xor_sync(0xffffffffu, acc[i], o);
    }
    if (lane==0){
      float tn = sqrtf(acc[0]);
      int amL=0; float mvL=3.4e38f;
      #pragma unroll
      for (int j=0;j<4;j++){
        float den = fmaxf(tn*snrm[j], 1e-8f);
        float s = acc[1+j]/den;
        if (s<mvL){ mvL=s; amL=j; }
      }
      g_minL[bt]=amL;
      int amI=0; float mvI=3.4e38f;
      #pragma unroll
      for (int j=0;j<4;j++){
        float den = fmaxf(tn*snrm[4+j], 1e-8f);
        float s = acc[5+j]/den;
        if (s<mvI){ mvI=s; amI=j; }
      }
      g_minI[bt]=amI;
    }
  }
}

// ======================= HMMA GEMM (M128xN128, pure fp16, K-step 64, 12 stages) =======================
#define APAD 72
#define TILE_E (128*APAD)
#define BUF_E  (2*TILE_E)
#define NBUF 2
#define GEMM_SMEM (NBUF*BUF_E*2)   /* 73728 bytes */

__device__ __forceinline__ uint32_t smem_u32(const void* p){
  return (uint32_t)__cvta_generic_to_shared(p);
}
__device__ __forceinline__ void cp16(uint32_t dst, const void* src){
  asm volatile("cp.async.cg.shared.global [%0], [%1], 16;" :: "r"(dst), "l"(src));
}
__device__ __forceinline__ void cp_commit(){ asm volatile("cp.async.commit_group;"); }
__device__ __forceinline__ void cp_wait0(){ asm volatile("cp.async.wait_group 0;"); }
__device__ __forceinline__ void ldmx4(uint32_t a, uint32_t& r0, uint32_t& r1, uint32_t& r2, uint32_t& r3){
  asm volatile("ldmatrix.sync.aligned.m8n8.x4.shared.b16 {%0,%1,%2,%3}, [%4];"
    : "=r"(r0), "=r"(r1), "=r"(r2), "=r"(r3) : "r"(a));
}
__device__ __forceinline__ void mma16816(float* d, const uint32_t* a, uint32_t b0, uint32_t b1){
  asm volatile(
    "mma.sync.aligned.m16n8k16.row.col.f32.f16.f16.f32 "
    "{%0,%1,%2,%3}, {%4,%5,%6,%7}, {%8,%9}, {%0,%1,%2,%3};"
    : "+f"(d[0]), "+f"(d[1]), "+f"(d[2]), "+f"(d[3])
    : "r"(a[0]), "r"(a[1]), "r"(a[2]), "r"(a[3]), "r"(b0), "r"(b1));
}

__global__ void __launch_bounds__(256,2) k_gemm_mma(int layer,
    const float* __restrict__ asrc, const float* __restrict__ adst){
  extern __shared__ __half sm[];

  int tid = threadIdx.x;
  int wid = tid >> 5, lane = tid & 31;
  int wm = wid & 3, wn = wid >> 2;
  int bx = blockIdx.x;
  int by = blockIdx.y;

  const __half* wH = g_wh + (size_t)layer*HH*HH;

  int lrow[4], lcol[4];
  int mAr[4], nBr[4];
  uint32_t dOf[4];
  #pragma unroll
  for (int i=0;i<4;i++){
    int idx = tid + i*256;
    int r = idx >> 3;
    int c = (idx & 7) * 8;
    lrow[i]=r; lcol[i]=c;
    int ma = by*128 + r; if (ma >= MROWS) ma = MROWS-1;
    mAr[i] = ma;
    nBr[i] = bx*128 + r;
    dOf[i] = (uint32_t)(r*APAD + c)*2;
  }
  uint32_t sBase = smem_u32(sm);

  uint32_t aRow = (uint32_t)(wm*32 + ((lane>>3)&1)*8 + (lane&7));
  uint32_t aCol = (uint32_t)(((lane>>4)&1)*8);
  uint32_t bRow = (uint32_t)(wn*64 + ((lane>>4)&1)*8 + (lane&7));
  uint32_t bCol = (uint32_t)(((lane>>3)&1)*8);

  float acc[2][8][4];
  #pragma unroll
  for (int i=0;i<2;i++)
    #pragma unroll
    for (int j=0;j<8;j++)
      #pragma unroll
      for (int k=0;k<4;k++) acc[i][j][k]=0.f;

  const int NSTAGE = 12;
  auto issue = [&](int s){
    int k0 = s * 64;
    uint32_t off = sBase + (uint32_t)((s & 1) * BUF_E) * 2;
    #pragma unroll
    for (int i=0;i<4;i++)
      cp16(off + dOf[i], g_hh + (size_t)mAr[i]*HH + k0 + lcol[i]);
    #pragma unroll
    for (int i=0;i<4;i++)
      cp16(off + TILE_E*2 + dOf[i], wH + (size_t)nBr[i]*HH + k0 + lcol[i]);
    cp_commit();
  };

  issue(0);
  for (int s = 0; s < NSTAGE; s++){
    cp_wait0();
    __syncthreads();
    if (s+1 < NSTAGE) issue(s+1);
    uint32_t buf = sBase + (uint32_t)((s & 1) * BUF_E) * 2;
    uint32_t tA = buf, tB = buf + TILE_E*2;
    #pragma unroll
    for (int kk = 0; kk < 64; kk += 16){
      uint32_t a[2][4], b[4][4];
      #pragma unroll
      for (int mt=0; mt<2; mt++){
        uint32_t ro = ((aRow + mt*16)*APAD + aCol + kk)*2;
        ldmx4(tA + ro, a[mt][0], a[mt][1], a[mt][2], a[mt][3]);
      }
      #pragma unroll
      for (int nt=0; nt<4; nt++){
        uint32_t ro = ((bRow + nt*16)*APAD + bCol + kk)*2;
        ldmx4(tB + ro, b[nt][0], b[nt][1], b[nt][2], b[nt][3]);
      }
      #pragma unroll
      for (int mt=0; mt<2; mt++)
        #pragma unroll
        for (int n=0; n<8; n++){
          int nt = n >> 1, pr = n & 1;
          mma16816(acc[mt][n], a[mt], b[nt][pr*2], b[nt][pr*2+1]);
        }
    }
  }

  // epilogue 1: write accumulators to g_hw
  #pragma unroll
  for (int mt=0; mt<2; mt++){
    int rr = by*128 + wm*32 + mt*16 + (lane>>2);
    #pragma unroll
    for (int n=0; n<8; n++){
      int c0 = bx*128 + wn*64 + n*8 + (lane&3)*2;
      if (rr < MROWS)
        *(float2*)(g_hw + (size_t)rr*HH + c0) = make_float2(acc[mt][n][0], acc[mt][n][1]);
      if (rr+8 < MROWS)
        *(float2*)(g_hw + (size_t)(rr+8)*HH + c0) = make_float2(acc[mt][n][2], acc[mt][n][3]);
    }
  }

  // epilogue 2: fused es/ed reduction
  int head = (bx*128 + wn*64) / DH;
  #pragma unroll
  for (int mt=0; mt<2; mt++){
    float ses0=0.f, sed0=0.f, ses1=0.f, sed1=0.f;
    #pragma unroll
    for (int n=0; n<8; n++){
      int c = bx*128 + wn*64 + n*8 + (lane&3)*2;
      float a0=asrc[c], a1=asrc[c+1], dd0=adst[c], dd1=adst[c+1];
      ses0 += acc[mt][n][0]*a0 + acc[mt][n][1]*a1;
      sed0 += acc[mt][n][0]*dd0 + acc[mt][n][1]*dd1;
      ses1 += acc[mt][n][2]*a0 + acc[mt][n][3]*a1;
      sed1 += acc[mt][n][2]*dd0 + acc[mt][n][3]*dd1;
    }
    #pragma unroll
    for (int o=1; o<=2; o<<=1){
      ses0 += __shfl_xor_sync(0xffffffffu, ses0, o);
      sed0 += __shfl_xor_sync(0xffffffffu, sed0, o);
      ses1 += __shfl_xor_sync(0xffffffffu, ses1, o);
      sed1 += __shfl_xor_sync(0xffffffffu, sed1, o);
    }
    if ((lane&3)==0){
      int rr = by*128 + wm*32 + mt*16 + (lane>>2);
      if (rr < MROWS){
        atomicAdd(&g_es[rr*NHEAD+head], ses0);
        atomicAdd(&g_ed[rr*NHEAD+head], sed0);
      }
      if (rr+8 < MROWS){
        atomicAdd(&g_es[(rr+8)*NHEAD+head], ses1);
        atomicAdd(&g_ed[(rr+8)*NHEAD+head], sed1);
      }
    }
  }
}

// 8 static in-edges for big node j (0..3 = label j, 4..7 = image j-4)
__device__ __forceinline__ int static_src(int j,int s){
  if (j<LLn){
    if (s<4) return TT+LLn+s;
    if (s<7){ int p=s-4; if(p>=j)p++; return TT+p; }
    return TT+j;
  } else {
    int jj=j-LLn;
    if (s<4) return TT+s;
    if (s<7){ int p=s-4; if(p>=jj)p++; return TT+LLn+p; }
    return TT+LLn+jj;
  }
}

// ---------------- big-node softmax max & sumexp (and zero agg) ----------------
__global__ void k_ms(){
  int b = blockIdx.x>>3, j = blockIdx.x&7;
  int tid = threadIdx.x;
  int jj = (j<LLn)? j : j-LLn;
  int dst = (j<LLn)? (TT+j) : (TT+LLn+jj);
  for (int c=tid;c<HH;c+=256) g_agg[blockIdx.x*HH+c]=0.f;
  float edv[4];
  #pragma unroll
  for (int h=0;h<4;h++) edv[h]=g_ed[(size_t)(b*NN+dst)*NHEAD+h];
  const int* minA = (j<LLn)? (g_minL+b*TT) : (g_minI+b*TT);
  float mx[4]={-3.4e38f,-3.4e38f,-3.4e38f,-3.4e38f};
  for (int t=tid;t<TT;t+=256){
    if (minA[t]!=jj){
      const float* e = g_es + (size_t)(b*NN+t)*NHEAD;
      #pragma unroll
      for (int h=0;h<4;h++) mx[h]=fmaxf(mx[h], lrelu(e[h]+edv[h]));
    }
  }
  if (tid==0){
    #pragma unroll
    for (int s=0;s<8;s++){
      int sr = static_src(j,s);
      const float* e = g_es + (size_t)(b*NN+sr)*NHEAD;
      #pragma unroll
      for (int h=0;h<4;h++) mx[h]=fmaxf(mx[h], lrelu(e[h]+edv[h]));
    }
  }
  __shared__ float red[256][4];
  #pragma unroll
  for (int h=0;h<4;h++) red[tid][h]=mx[h];
  __syncthreads();
  for (int st=128;st>0;st>>=1){
    if (tid<st){
      #pragma unroll
      for (int h=0;h<4;h++) red[tid][h]=fmaxf(red[tid][h],red[tid+st][h]);
    }
    __syncthreads();
  }
  float mv[4];
  #pragma unroll
  for (int h=0;h<4;h++) mv[h]=red[0][h];
  __syncthreads();
  float sm[4]={0.f,0.f,0.f,0.f};
  for (int t=tid;t<TT;t+=256){
    if (minA[t]!=jj){
      const float* e = g_es + (size_t)(b*NN+t)*NHEAD;
      #pragma unroll
      for (int h=0;h<4;h++) sm[h] += __expf(lrelu(e[h]+edv[h])-mv[h]);
    }
  }
  if (tid==0){
    #pragma unroll
    for (int s=0;s<8;s++){
      int sr = static_src(j,s);
      const float* e = g_es + (size_t)(b*NN+sr)*NHEAD;
      #pragma unroll
      for (int h=0;h<4;h++) sm[h] += __expf(lrelu(e[h]+edv[h])-mv[h]);
    }
  }
  #pragma unroll
  for (int h=0;h<4;h++) red[tid][h]=sm[h];
  __syncthreads();
  for (int st=128;st>0;st>>=1){
    if (tid<st){
      #pragma unroll
      for (int h=0;h<4;h++) red[tid][h]+=red[tid+st][h];
    }
    __syncthreads();
  }
  if (tid<4){
    g_m[(b*8+j)*NHEAD+tid]=mv[tid];
    g_s[(b*8+j)*NHEAD+tid]=red[0][tid];
  }
}

// ---------------- big-node weighted aggregation (all 8 j per block, alpha inline) ----------------
__global__ void k_agg(){
  int b  = blockIdx.x >> 5;
  int sp = blockIdx.x & 31;
  int tid = threadIdx.x;
  int t0 = sp*32;
  __shared__ float sal[32][8][4];
  #pragma unroll
  for (int q=0;q<4;q++){
    int idx = tid + q*256;
    int tl = idx >> 5;
    int j  = (idx >> 2) & 7;
    int h  = idx & 3;
    int jj = (j<LLn)? j : j-LLn;
    int dst = (j<LLn)? (TT+j) : (TT+LLn+jj);
    int t = t0 + tl;
    int excl = (j<LLn)? (g_minL[b*TT+t]==jj) : (g_minI[b*TT+t]==jj);
    float al = 0.f;
    if (!excl){
      float e = lrelu(g_es[(size_t)(b*NN+t)*NHEAD+h] + g_ed[(size_t)(b*NN+dst)*NHEAD+h]);
      al = __expf(e - g_m[(b*8+j)*NHEAD+h]) / g_s[(b*8+j)*NHEAD+h];
    }
    sal[tl][j][h] = al;
  }
  __syncthreads();
  int c0=tid, c1=tid+256, c2=tid+512;
  int h0=c0/DH, h1=c1/DH, h2=c2/DH;
  float a0[8], a1[8], a2[8];
  #pragma unroll
  for (int j=0;j<8;j++){ a0[j]=0.f; a1[j]=0.f; a2[j]=0.f; }
  for (int tl=0; tl<32; tl++){
    const float* hr = g_hw + (size_t)(b*NN + t0+tl)*HH;
    float v0=hr[c0], v1=hr[c1], v2=hr[c2];
    #pragma unroll
    for (int j=0;j<8;j++){
      a0[j] += sal[tl][j][h0]*v0;
      a1[j] += sal[tl][j][h1]*v1;
      a2[j] += sal[tl][j][h2]*v2;
    }
  }
  #pragma unroll
  for (int j=0;j<8;j++){
    atomicAdd(&g_agg[(b*8+j)*HH+c0], a0[j]);
    atomicAdd(&g_agg[(b*8+j)*HH+c1], a1[j]);
    atomicAdd(&g_agg[(b*8+j)*HH+c2], a2[j]);
  }
}

// ---------------- big-node epilogue: static edges + bias+relu+residual+LN (+conv) ----------------
__global__ void k_big(const float* __restrict__ bias,const float* __restrict__ lng,
                      const float* __restrict__ lnb){
  int b = blockIdx.x>>3, j = blockIdx.x&7;
  int jj = (j<LLn)? j : j-LLn;
  int node = (j<LLn)? (TT+j) : (TT+LLn+jj);
  int tid = threadIdx.x;
  __shared__ float sal[8][4];
  __shared__ int ssrc[8];
  if (tid<32){
    int s=tid>>2, h=tid&3;
    int sr = static_src(j,s);
    if (h==0) ssrc[s]=sr;
    float e = lrelu(g_es[(size_t)(b*NN+sr)*NHEAD+h] + g_ed[(size_t)(b*NN+node)*NHEAD+h]);
    sal[s][h] = __expf(e - g_m[(b*8+j)*NHEAD+h]) / g_s[(b*8+j)*NHEAD+h];
  }
  __syncthreads();
  size_t row = (size_t)(b*NN+node)*HH;
  float v[3]; float s=0.f, sq=0.f;
  #pragma unroll
  for (int r=0;r<3;r++){
    int c = tid + 256*r;
    int hd = c/DH;
    float o = g_agg[(b*8+j)*HH+c];
    #pragma unroll
    for (int e=0;e<8;e++)
      o += sal[e][hd] * g_hw[(size_t)(b*NN+ssrc[e])*HH + c];
    o = fmaxf(o + bias[c], 0.f);
    float y = o + g_h[row+c];
    v[r]=y; s+=y; sq+=y*y;
  }
  __shared__ float rs[256], rq[256];
  rs[tid]=s; rq[tid]=sq; __syncthreads();
  for (int st=128;st>0;st>>=1){
    if (tid<st){ rs[tid]+=rs[tid+st]; rq[tid]+=rq[tid+st]; }
    __syncthreads();
  }
  float mu = rs[0]*(1.f/HH);
  float var = rq[0]*(1.f/HH) - mu*mu;
  float rstd = rsqrtf(var + 1e-5f);
  #pragma unroll
  for (int r=0;r<3;r++){
    int c = tid + 256*r;
    float y = (v[r]-mu)*rstd*lng[c] + lnb[c];
    g_h[row+c] = y;
    g_hh[row+c] = __float2half(y);
  }
}

// ---------------- text-node: block = (b, 8 tokens); big rows staged in 24KB SMEM ----------------
__global__ void __launch_bounds__(256) k_text(const float* __restrict__ bias,
                       const float* __restrict__ lng, const float* __restrict__ lnb,
                       float* __restrict__ outp, int last){
  __shared__ float sbig[8*HH];            // 24 KB: label rows 0-3, image rows 4-7
  __shared__ float salc[8][3][4];
  __shared__ float salb[8][6][4];
  int blk = blockIdx.x;
  int b = blk >> 7;
  int t0 = (blk & 127) * 8;
  int tid = threadIdx.x;
  int w = tid >> 5, lane = tid & 31;
  const float4* hw4 = (const float4*)(g_hw + (size_t)b*NN*HH);

  for (int i = tid; i < 8*(HH/4); i += 256){
    int r = i / (HH/4), c4 = i % (HH/4);
    ((float4*)sbig)[i] = hw4[(size_t)(TT + r)*(HH/4) + c4];
  }
  __syncthreads();

  int t = t0 + w;
  int bt = b*TT + t;
  int csrc[3]; int ncs = 0;
  csrc[ncs++] = t;
  if (t > 0)    csrc[ncs++] = t-1;
  if (t < TT-1) csrc[ncs++] = t+1;
  int ml = g_minL[bt], mi = g_minI[bt];
  int bsrc[6]; int nbs = 0;
  #pragma unroll
  for (int j=0;j<4;j++) if (j != ml) bsrc[nbs++] = j;
  #pragma unroll
  for (int j=0;j<4;j++) if (j != mi) bsrc[nbs++] = 4+j;

  if (lane < 4){
    float ed = g_ed[(size_t)(b*NN+t)*NHEAD + lane];
    float ev[9]; float mx = -3.4e38f;
    for (int e=0;e<ncs;e++){
      float x = lrelu(g_es[(size_t)(b*NN+csrc[e])*NHEAD + lane] + ed);
      ev[e]=x; mx=fmaxf(mx,x);
    }
    for (int e=0;e<nbs;e++){
      float x = lrelu(g_es[(size_t)(b*NN+TT+bsrc[e])*NHEAD + lane] + ed);
      ev[ncs+e]=x; mx=fmaxf(mx,x);
    }
    float sm=0.f;
    int ns = ncs + nbs;
    for (int e=0;e<ns;e++){ float wv=__expf(ev[e]-mx); ev[e]=wv; sm+=wv; }
    float inv = 1.f/sm;
    for (int e=0;e<ncs;e++) salc[w][e][lane] = ev[e]*inv;
    for (int e=0;e<nbs;e++) salb[w][e][lane] = ev[ncs+e]*inv;
  }
  __syncwarp();

  size_t row = (size_t)(b*NN+t)*HH;
  const float4* gh4 = (const float4*)(g_h + row);
  const float4* bias4 = (const float4*)bias;
  const float4* sbig4 = (const float4*)sbig;
  float4 v[6]; float s=0.f, sq=0.f;
  #pragma unroll
  for (int i=0;i<6;i++){
    int c4 = lane + i*32;
    int hd = c4 / 48;
    float4 a = make_float4(0.f,0.f,0.f,0.f);
    for (int e=0;e<ncs;e++){
      float wv = salc[w][e][hd];
      float4 p = hw4[(size_t)csrc[e]*(HH/4) + c4];
      a.x += wv*p.x; a.y += wv*p.y; a.z += wv*p.z; a.w += wv*p.w;
    }
    for (int e=0;e<nbs;e++){
      float wv = salb[w][e][hd];
      float4 p = sbig4[bsrc[e]*(HH/4) + c4];
      a.x += wv*p.x; a.y += wv*p.y; a.z += wv*p.z; a.w += wv*p.w;
    }
    float4 bb = bias4[c4];
    float4 hh = gh4[c4];
    float4 y;
    y.x = fmaxf(a.x + bb.x, 0.f) + hh.x;
    y.y = fmaxf(a.y + bb.y, 0.f) + hh.y;
    y.z = fmaxf(a.z + bb.z, 0.f) + hh.z;
    y.w = fmaxf(a.w + bb.w, 0.f) + hh.w;
    v[i] = y;
    s  += y.x + y.y + y.z + y.w;
    sq += y.x*y.x + y.y*y.y + y.z*y.z + y.w*y.w;
  }
  #pragma unroll
  for (int o=16;o>0;o>>=1){
    s  += __shfl_xor_sync(0xffffffffu, s, o);
    sq += __shfl_xor_sync(0xffffffffu, sq, o);
  }
  float mu = s*(1.f/HH);
  float var = sq*(1.f/HH) - mu*mu;
  float rstd = rsqrtf(var + 1e-5f);
  const float4* lng4 = (const float4*)lng;
  const float4* lnb4 = (const float4*)lnb;
  if (last){
    float4* od = (float4*)(outp + ((size_t)bt)*HH);
    #pragma unroll
    for (int i=0;i<6;i++){
      int c4 = lane + i*32;
      float4 g = lng4[c4], bb = lnb4[c4];
      float4 y;
      y.x = (v[i].x-mu)*rstd*g.x + bb.x;
      y.y = (v[i].y-mu)*rstd*g.y + bb.y;
      y.z = (v[i].z-mu)*rstd*g.z + bb.z;
      y.w = (v[i].w-mu)*rstd*g.w + bb.w;
      od[c4] = y;
    }
  } else {
    float4* gh4w = (float4*)(g_h + row);
    uint2* hh2 = (uint2*)(g_hh + row);
    #pragma unroll
    for (int i=0;i<6;i++){
      int c4 = lane + i*32;
      float4 g = lng4[c4], bb = lnb4[c4];
      float4 y;
      y.x = (v[i].x-mu)*rstd*g.x + bb.x;
      y.y = (v[i].y-mu)*rstd*g.y + bb.y;
      y.z = (v[i].z-mu)*rstd*g.z + bb.z;
      y.w = (v[i].w-mu)*rstd*g.w + bb.w;
      gh4w[c4] = y;
      __half2 lo = __floats2half2_rn(y.x, y.y);
      __half2 hi = __floats2half2_rn(y.z, y.w);
      uint2 pk;
      pk.x = *(uint32_t*)&lo;
      pk.y = *(uint32_t*)&hi;
      hh2[c4] = pk;
    }
  }
}

extern "C" void kernel_launch(void* const* d_in, const int* in_sizes, int n_in,
                              void* d_out, int out_size) {
  const float* text = (const float*)d_in[0];
  const float* lab  = (const float*)d_in[1];
  const float* img  = (const float*)d_in[2];
  const float* W    = (const float*)d_in[3];
  const float* asrc = (const float*)d_in[4];
  const float* adst = (const float*)d_in[5];
  const float* bias = (const float*)d_in[6];
  const float* lng  = (const float*)d_in[7];
  const float* lnb  = (const float*)d_in[8];
  float* out = (float*)d_out;

  cudaFuncSetAttribute(k_gemm_mma, cudaFuncAttributeMaxDynamicSharedMemorySize, GEMM_SMEM);

  // launch order keeps the GEMM at profiled slot 4
  k_pack<<<(MROWS*(HH/4)+255)/256, 256>>>(text, lab, img);
  k_cvtW<<<dim3(24,24,3), dim3(32,32)>>>(W);
  k_norm<<<BB*8, 128>>>(lab, img);
  k_gemm_mma<<<dim3(6,65), 256, GEMM_SMEM>>>(0, asrc, adst);
  k_topk<<<BB*32, 256>>>(text, lab, img);

  for (int l=0; l<NLAY; l++){
    int last = (l == NLAY-1);
    if (l > 0){
      k_zero<<<(MROWS*NHEAD+255)/256, 256>>>();
      k_gemm_mma<<<dim3(6,65), 256, GEMM_SMEM>>>(l, asrc + l*NHEAD*DH, adst + l*NHEAD*DH);
    }
    if (!last){
      k_ms<<<BB*8, 256>>>();
      k_agg<<<BB*32, 256>>>();
      k_big<<<BB*8, 256>>>(bias + l*HH, lng + l*HH, lnb + l*HH);
    }
    k_text<<<BB*128, 256>>>(bias + l*HH, lng + l*HH, lnb + l*HH, out, last);
  }
}